// round 14
// baseline (speedup 1.0000x reference)
#include <cuda_runtime.h>
#include <cuda_bf16.h>
#include <math.h>

#define Nn 100000
#define Ee 1600000
#define Gg 64
#define Cc 40
#define EPSb 1e-5f

// ---------------- scratch ----------------
__device__ __align__(128) float g_deg[Nn];
__device__ __align__(128) int   g_cnt[Nn];
__device__ __align__(128) int   g_off[Nn];
__device__ __align__(128) int   g_cur[Nn];
__device__ __align__(128) int   g_rowS[Ee];
__device__ __align__(128) float g_wS[Ee];
__device__ __align__(128) float g_hcat1[Nn * 48];            // h1|h2|h3 (16 each)
__device__ __align__(128) float g_hcat2[(size_t)Nn * 384];   // h1|h2|h3 (128 each)
__device__ __align__(128) float g_xcat[(size_t)Nn * 256];
__device__ __align__(128) float g_stats[1024];
__device__ __align__(128) float g_bnsc[256];
__device__ __align__(128) float g_bnsh[256];
__device__ __align__(128) int   g_pmax[Gg * 256];
__device__ __align__(128) int   g_pmin[Gg * 256];
__device__ __align__(128) float g_pooled[Gg * 256];
__device__ __align__(128) float g_f1[Gg * 256];
__device__ __align__(128) float g_f2[Gg * 128];
__device__ __align__(128) unsigned short g_W2bh[512 * 128];
__device__ __align__(128) unsigned short g_W2bl[512 * 128];
__device__ __align__(128) unsigned short g_Wlbh[256 * 256];
__device__ __align__(128) unsigned short g_Wlbl[256 * 256];
__device__ __align__(128) unsigned short g_W1bh[64 * 128];
__device__ __align__(128) unsigned short g_W1bl[64 * 128];

// ---------------- helpers ----------------
__device__ __forceinline__ unsigned int smem_u32(const void* p) {
    unsigned int a;
    asm("{ .reg .u64 t; cvta.to.shared.u64 t, %1; cvt.u32.u64 %0, t; }" : "=r"(a) : "l"(p));
    return a;
}
__device__ __forceinline__ void cvt_hilo(float a, unsigned short& h, unsigned short& l) {
    __nv_bfloat16 bh = __float2bfloat16(a);
    float r = a - __bfloat162float(bh);
    __nv_bfloat16 bl = __float2bfloat16(r);
    h = __bfloat16_as_ushort(bh);
    l = __bfloat16_as_ushort(bl);
}
__device__ __forceinline__ void ldm_x4(unsigned int* r, unsigned int addr) {
    asm volatile("ldmatrix.sync.aligned.m8n8.x4.shared.b16 {%0,%1,%2,%3}, [%4];"
                 : "=r"(r[0]), "=r"(r[1]), "=r"(r[2]), "=r"(r[3]) : "r"(addr));
}
__device__ __forceinline__ void ldm_x4t(unsigned int* r, unsigned int addr) {
    asm volatile("ldmatrix.sync.aligned.m8n8.x4.trans.shared.b16 {%0,%1,%2,%3}, [%4];"
                 : "=r"(r[0]), "=r"(r[1]), "=r"(r[2]), "=r"(r[3]) : "r"(addr));
}
__device__ __forceinline__ void mma_bf16(float* c, const unsigned int* a, const unsigned int* b) {
    asm volatile(
        "mma.sync.aligned.m16n8k16.row.col.f32.bf16.bf16.f32 "
        "{%0,%1,%2,%3}, {%4,%5,%6,%7}, {%8,%9}, {%0,%1,%2,%3};"
        : "+f"(c[0]), "+f"(c[1]), "+f"(c[2]), "+f"(c[3])
        : "r"(a[0]), "r"(a[1]), "r"(a[2]), "r"(a[3]), "r"(b[0]), "r"(b[1]));
}

// ---------------- graph preprocessing ----------------
__global__ __launch_bounds__(256) void k_deg_hist(const int* __restrict__ col,
                                                  const float* __restrict__ ea) {
    int e = blockIdx.x * blockDim.x + threadIdx.x;
    if (e >= Ee) return;
    int c = col[e];
    atomicAdd(&g_deg[c], ea[e]);
    atomicAdd(&g_cnt[c], 1);
}

__global__ __launch_bounds__(256) void k_scan() {
    __shared__ int ss[256];
    const int CH = (Nn + 255) / 256;
    int t = threadIdx.x;
    int base = t * CH;
    int s = 0;
    for (int i = 0; i < CH; i++) { int idx = base + i; if (idx < Nn) s += g_cnt[idx]; }
    ss[t] = s;
    __syncthreads();
    int own = s;
    for (int o = 1; o < 256; o <<= 1) {
        int v = (t >= o) ? ss[t - o] : 0;
        __syncthreads();
        ss[t] += v;
        __syncthreads();
    }
    int run = ss[t] - own;
    for (int i = 0; i < CH; i++) {
        int idx = base + i;
        if (idx < Nn) { g_off[idx] = run; run += g_cnt[idx]; }
    }
}

__global__ __launch_bounds__(256) void k_scatter(const int* __restrict__ row,
                                                 const int* __restrict__ col,
                                                 const float* __restrict__ ea) {
    int e = blockIdx.x * blockDim.x + threadIdx.x;
    if (e >= Ee) return;
    int r = row[e], c = col[e];
    float dr = g_deg[r], dc = g_deg[c];
    float ir = dr > 0.f ? rsqrtf(dr) : 0.f;
    float ic = dc > 0.f ? rsqrtf(dc) : 0.f;
    float w = ir * ea[e] * ic;
    int p = g_off[c] + atomicAdd(&g_cur[c], 1);
    g_rowS[p] = r;
    g_wS[p] = w;
}

// CSR gather propagation within hcat (hops 2,3)
template <int TPN>
__global__ __launch_bounds__(256) void k_prop(float* __restrict__ hbase, int stride,
                                              int so, int dofs) {
    int gid = blockIdx.x * blockDim.x + threadIdx.x;
    int node = gid / TPN;
    int part = gid % TPN;
    if (node >= Nn) return;
    int s = g_off[node];
    int e = s + g_cnt[node];
    float4 acc = make_float4(0.f, 0.f, 0.f, 0.f);
    int so4 = so + part * 4;
    for (int i = s; i < e; i++) {
        int r = __ldg(&g_rowS[i]);
        float w = __ldg(&g_wS[i]);
        const float4 v = *reinterpret_cast<const float4*>(hbase + (size_t)r * stride + so4);
        acc.x = fmaf(w, v.x, acc.x);
        acc.y = fmaf(w, v.y, acc.y);
        acc.z = fmaf(w, v.z, acc.z);
        acc.w = fmaf(w, v.w, acc.w);
    }
    *reinterpret_cast<float4*>(hbase + (size_t)node * stride + dofs + part * 4) = acc;
}

// Hop 1: gather from external src (optional algebraic BN), write h1 into hcat.
template <int TPN, bool BN>
__global__ __launch_bounds__(256) void k_prop_x(const float* __restrict__ src, int sstride,
                                                float* __restrict__ hbase, int stride,
                                                const float* __restrict__ bnsc,
                                                const float* __restrict__ bnsh) {
    int gid = blockIdx.x * blockDim.x + threadIdx.x;
    int node = gid / TPN;
    int part = gid % TPN;
    if (node >= Nn) return;
    int c4 = part * 4;
    float4 sc4, sh4;
    if (BN) {
        sc4 = *reinterpret_cast<const float4*>(&bnsc[c4]);
        sh4 = *reinterpret_cast<const float4*>(&bnsh[c4]);
    }
    int s = g_off[node];
    int e = s + g_cnt[node];
    float4 acc = make_float4(0.f, 0.f, 0.f, 0.f);
    float wsum = 0.f;
    for (int i = s; i < e; i++) {
        int r = __ldg(&g_rowS[i]);
        float w = __ldg(&g_wS[i]);
        const float4 v = *reinterpret_cast<const float4*>(src + (size_t)r * sstride + c4);
        acc.x = fmaf(w, v.x, acc.x);
        acc.y = fmaf(w, v.y, acc.y);
        acc.z = fmaf(w, v.z, acc.z);
        acc.w = fmaf(w, v.w, acc.w);
        if (BN) wsum += w;
    }
    if (BN) {
        acc.x = fmaf(acc.x, sc4.x, sh4.x * wsum);
        acc.y = fmaf(acc.y, sc4.y, sh4.y * wsum);
        acc.z = fmaf(acc.z, sc4.z, sh4.z * wsum);
        acc.w = fmaf(acc.w, sc4.w, sh4.w * wsum);
    }
    *reinterpret_cast<float4*>(hbase + (size_t)node * stride + part * 4) = acc;
}

// ---------------- weights -> bf16 hi/lo images ----------------
__global__ __launch_bounds__(256) void k_prepWbf(const float* __restrict__ W,
                                                 unsigned short* __restrict__ oh,
                                                 unsigned short* __restrict__ ol, int n) {
    int idx = blockIdx.x * blockDim.x + threadIdx.x;
    if (idx >= n) return;
    unsigned short h, l;
    cvt_hilo(W[idx], h, l);
    oh[idx] = h;
    ol[idx] = l;
}

// =====================================================================
// shared smem layout constants for mma kernels
// =====================================================================
#define MMA_A_HI 0
#define MMA_A_LO 18432
#define MMA_B_HI 36864
#define MMA_B_LO 54272
#define MMA_SMEM 71680

// =====================================================================
// conv2 GEMM via mma.sync bf16 split.
// A chunks 0-1 read xcat (BN in registers); chunks 2-7 read hcat2 (384-wide).
// =====================================================================
__global__ __launch_bounds__(256) void k_gemm_conv2_mma(const float* __restrict__ Xc,
                                                        const float* __restrict__ H,
                                                        const float* __restrict__ bias,
                                                        float* __restrict__ C) {
    extern __shared__ char smem[];
    __shared__ float sc1[128], sh1[128];
    unsigned int sb = smem_u32(smem);
    int tid = threadIdx.x;
    int lane = tid & 31;
    int wid = tid >> 5;
    int warp_m = wid & 3;
    int warp_n = wid >> 2;
    int row0 = blockIdx.x * 128;
    if (tid < 128) {
        sc1[tid] = g_bnsc[tid];
        sh1[tid] = g_bnsh[tid];
    }
    __syncthreads();

    float acc[2][8][4];
#pragma unroll
    for (int mt = 0; mt < 2; mt++)
#pragma unroll
        for (int nt = 0; nt < 8; nt++)
#pragma unroll
            for (int j = 0; j < 4; j++) acc[mt][nt][j] = 0.f;

    int col4 = tid & 15;
    int rbase = tid >> 4;

    for (int c = 0; c < 8; c++) {
        int kbase = c * 64;
#pragma unroll
        for (int i = 0; i < 8; i++) {
            int r = rbase + i * 16;
            int grow = row0 + r;
            float4 v = make_float4(0.f, 0.f, 0.f, 0.f);
            if (grow < Nn) {
                if (c < 2) {
                    int kc = kbase + col4 * 4;   // 0..124
                    v = *reinterpret_cast<const float4*>(&Xc[(size_t)grow * 256 + kc]);
                    v.x = fmaf(v.x, sc1[kc],     sh1[kc]);
                    v.y = fmaf(v.y, sc1[kc + 1], sh1[kc + 1]);
                    v.z = fmaf(v.z, sc1[kc + 2], sh1[kc + 2]);
                    v.w = fmaf(v.w, sc1[kc + 3], sh1[kc + 3]);
                } else {
                    v = *reinterpret_cast<const float4*>(
                        &H[(size_t)grow * 384 + kbase - 128 + col4 * 4]);
                }
            }
            unsigned short h0, l0, h1, l1, h2, l2, h3, l3;
            cvt_hilo(v.x, h0, l0);
            cvt_hilo(v.y, h1, l1);
            cvt_hilo(v.z, h2, l2);
            cvt_hilo(v.w, h3, l3);
            int ob = r * 144 + col4 * 8;
            *reinterpret_cast<uint2*>(smem + MMA_A_HI + ob) =
                make_uint2((unsigned)h0 | ((unsigned)h1 << 16), (unsigned)h2 | ((unsigned)h3 << 16));
            *reinterpret_cast<uint2*>(smem + MMA_A_LO + ob) =
                make_uint2((unsigned)l0 | ((unsigned)l1 << 16), (unsigned)l2 | ((unsigned)l3 << 16));
        }
#pragma unroll
        for (int j = 0; j < 4; j++) {
            int idx = tid + j * 256;
            int kr = idx >> 4, c8 = idx & 15;
            int ob = kr * 272 + c8 * 16;
            *reinterpret_cast<uint4*>(smem + MMA_B_HI + ob) =
                *reinterpret_cast<const uint4*>(&g_W2bh[(kbase + kr) * 128 + c8 * 8]);
            *reinterpret_cast<uint4*>(smem + MMA_B_LO + ob) =
                *reinterpret_cast<const uint4*>(&g_W2bl[(kbase + kr) * 128 + c8 * 8]);
        }
        __syncthreads();

#pragma unroll
        for (int ks = 0; ks < 4; ks++) {
            unsigned int Ah[2][4], Al[2][4], Bf[4][4];
            int arow = (lane & 15);
            int acolb = ks * 32 + (lane >> 4) * 16;
#pragma unroll
            for (int mt = 0; mt < 2; mt++) {
                int m0 = warp_m * 32 + mt * 16;
                unsigned int aoff = (unsigned)((m0 + arow) * 144 + acolb);
                ldm_x4(Ah[mt], sb + MMA_A_HI + aoff);
                ldm_x4(Al[mt], sb + MMA_A_LO + aoff);
            }
            int brow = ks * 16 + (lane & 15);
#pragma unroll
            for (int p = 0; p < 4; p++) {
                unsigned int boff = (unsigned)(brow * 272 + (warp_n * 64 + p * 16 + (lane >> 4) * 8) * 2);
                ldm_x4t(Bf[p], sb + MMA_B_HI + boff);
            }
#pragma unroll
            for (int mt = 0; mt < 2; mt++)
#pragma unroll
                for (int p = 0; p < 4; p++) {
                    mma_bf16(acc[mt][2 * p],     Ah[mt], &Bf[p][0]);
                    mma_bf16(acc[mt][2 * p + 1], Ah[mt], &Bf[p][2]);
                    mma_bf16(acc[mt][2 * p],     Al[mt], &Bf[p][0]);
                    mma_bf16(acc[mt][2 * p + 1], Al[mt], &Bf[p][2]);
                }
#pragma unroll
            for (int p = 0; p < 4; p++) {
                unsigned int boff = (unsigned)(brow * 272 + (warp_n * 64 + p * 16 + (lane >> 4) * 8) * 2);
                ldm_x4t(Bf[p], sb + MMA_B_LO + boff);
            }
#pragma unroll
            for (int mt = 0; mt < 2; mt++)
#pragma unroll
                for (int p = 0; p < 4; p++) {
                    mma_bf16(acc[mt][2 * p],     Ah[mt], &Bf[p][0]);
                    mma_bf16(acc[mt][2 * p + 1], Ah[mt], &Bf[p][2]);
                }
        }
        __syncthreads();
    }

#pragma unroll
    for (int mt = 0; mt < 2; mt++) {
        int r0 = row0 + warp_m * 32 + mt * 16 + (lane >> 2);
#pragma unroll
        for (int nt = 0; nt < 8; nt++) {
            int colc = warp_n * 64 + nt * 8 + (lane & 3) * 2;
            float b0 = __ldg(&bias[colc]), b1 = __ldg(&bias[colc + 1]);
            if (r0 < Nn) {
                float2 o = make_float2(fmaxf(acc[mt][nt][0] + b0, 0.f),
                                       fmaxf(acc[mt][nt][1] + b1, 0.f));
                *reinterpret_cast<float2*>(&C[(size_t)r0 * 256 + colc]) = o;
            }
            if (r0 + 8 < Nn) {
                float2 o = make_float2(fmaxf(acc[mt][nt][2] + b0, 0.f),
                                       fmaxf(acc[mt][nt][3] + b1, 0.f));
                *reinterpret_cast<float2*>(&C[(size_t)(r0 + 8) * 256 + colc]) = o;
            }
        }
    }
}

// =====================================================================
// conv1 GEMM via mma.sync bf16 split, K=64; A cols 0-15 from x,
// 16-63 from hcat1 (48-wide). Staged-stats epilogue.
// =====================================================================
#define CMA_RED 67584
#define CMA_SMEM 71680

__global__ __launch_bounds__(256) void k_gemm_conv1_mma(const float* __restrict__ X,
                                                        const float* __restrict__ H,
                                                        const float* __restrict__ bias,
                                                        float* __restrict__ C,
                                                        float* __restrict__ sS,
                                                        float* __restrict__ sQ) {
    extern __shared__ char smem[];
    unsigned int sb = smem_u32(smem);
    int tid = threadIdx.x;
    int lane = tid & 31;
    int wid = tid >> 5;
    int warp_m = wid & 3;
    int warp_n = wid >> 2;
    int row0 = blockIdx.x * 128;

    float acc[2][8][4];
#pragma unroll
    for (int mt = 0; mt < 2; mt++)
#pragma unroll
        for (int nt = 0; nt < 8; nt++)
#pragma unroll
            for (int j = 0; j < 4; j++) acc[mt][nt][j] = 0.f;

    int col4 = tid & 15;
    int rbase = tid >> 4;

#pragma unroll
    for (int i = 0; i < 8; i++) {
        int r = rbase + i * 16;
        int grow = row0 + r;
        float4 v = make_float4(0.f, 0.f, 0.f, 0.f);
        if (grow < Nn) {
            if (col4 < 4)
                v = *reinterpret_cast<const float4*>(&X[(size_t)grow * 16 + col4 * 4]);
            else
                v = *reinterpret_cast<const float4*>(&H[(size_t)grow * 48 + col4 * 4 - 16]);
        }
        unsigned short h0, l0, h1, l1, h2, l2, h3, l3;
        cvt_hilo(v.x, h0, l0);
        cvt_hilo(v.y, h1, l1);
        cvt_hilo(v.z, h2, l2);
        cvt_hilo(v.w, h3, l3);
        int ob = r * 144 + col4 * 8;
        *reinterpret_cast<uint2*>(smem + MMA_A_HI + ob) =
            make_uint2((unsigned)h0 | ((unsigned)h1 << 16), (unsigned)h2 | ((unsigned)h3 << 16));
        *reinterpret_cast<uint2*>(smem + MMA_A_LO + ob) =
            make_uint2((unsigned)l0 | ((unsigned)l1 << 16), (unsigned)l2 | ((unsigned)l3 << 16));
    }
#pragma unroll
    for (int j = 0; j < 4; j++) {
        int idx = tid + j * 256;
        int kr = idx >> 4, c8 = idx & 15;
        int ob = kr * 272 + c8 * 16;
        *reinterpret_cast<uint4*>(smem + MMA_B_HI + ob) =
            *reinterpret_cast<const uint4*>(&g_W1bh[kr * 128 + c8 * 8]);
        *reinterpret_cast<uint4*>(smem + MMA_B_LO + ob) =
            *reinterpret_cast<const uint4*>(&g_W1bl[kr * 128 + c8 * 8]);
    }
    __syncthreads();

#pragma unroll
    for (int ks = 0; ks < 4; ks++) {
        unsigned int Ah[2][4], Al[2][4], Bf[4][4];
        int arow = (lane & 15);
        int acolb = ks * 32 + (lane >> 4) * 16;
#pragma unroll
        for (int mt = 0; mt < 2; mt++) {
            int m0 = warp_m * 32 + mt * 16;
            unsigned int aoff = (unsigned)((m0 + arow) * 144 + acolb);
            ldm_x4(Ah[mt], sb + MMA_A_HI + aoff);
            ldm_x4(Al[mt], sb + MMA_A_LO + aoff);
        }
        int brow = ks * 16 + (lane & 15);
#pragma unroll
        for (int p = 0; p < 4; p++) {
            unsigned int boff = (unsigned)(brow * 272 + (warp_n * 64 + p * 16 + (lane >> 4) * 8) * 2);
            ldm_x4t(Bf[p], sb + MMA_B_HI + boff);
        }
#pragma unroll
        for (int mt = 0; mt < 2; mt++)
#pragma unroll
            for (int p = 0; p < 4; p++) {
                mma_bf16(acc[mt][2 * p],     Ah[mt], &Bf[p][0]);
                mma_bf16(acc[mt][2 * p + 1], Ah[mt], &Bf[p][2]);
                mma_bf16(acc[mt][2 * p],     Al[mt], &Bf[p][0]);
                mma_bf16(acc[mt][2 * p + 1], Al[mt], &Bf[p][2]);
            }
#pragma unroll
        for (int p = 0; p < 4; p++) {
            unsigned int boff = (unsigned)(brow * 272 + (warp_n * 64 + p * 16 + (lane >> 4) * 8) * 2);
            ldm_x4t(Bf[p], sb + MMA_B_LO + boff);
        }
#pragma unroll
        for (int mt = 0; mt < 2; mt++)
#pragma unroll
            for (int p = 0; p < 4; p++) {
                mma_bf16(acc[mt][2 * p],     Ah[mt], &Bf[p][0]);
                mma_bf16(acc[mt][2 * p + 1], Ah[mt], &Bf[p][2]);
            }
    }
    __syncthreads();

    float* stg = reinterpret_cast<float*>(smem);
    float* red = reinterpret_cast<float*>(smem + CMA_RED);
    red[tid] = 0.f;
#pragma unroll
    for (int mt = 0; mt < 2; mt++) {
        int rloc = warp_m * 32 + mt * 16 + (lane >> 2);
        int r0 = row0 + rloc;
#pragma unroll
        for (int nt = 0; nt < 8; nt++) {
            int cloc = warp_n * 64 + nt * 8 + (lane & 3) * 2;
            float b0 = __ldg(&bias[cloc]), b1 = __ldg(&bias[cloc + 1]);
            float o0 = fmaxf(acc[mt][nt][0] + b0, 0.f);
            float o1 = fmaxf(acc[mt][nt][1] + b1, 0.f);
            float o2 = fmaxf(acc[mt][nt][2] + b0, 0.f);
            float o3 = fmaxf(acc[mt][nt][3] + b1, 0.f);
            stg[rloc * 132 + cloc]           = o0;
            stg[rloc * 132 + cloc + 1]       = o1;
            stg[(rloc + 8) * 132 + cloc]     = o2;
            stg[(rloc + 8) * 132 + cloc + 1] = o3;
            if (r0 < Nn)
                *reinterpret_cast<float2*>(&C[(size_t)r0 * 256 + cloc]) = make_float2(o0, o1);
            if (r0 + 8 < Nn)
                *reinterpret_cast<float2*>(&C[(size_t)(r0 + 8) * 256 + cloc]) = make_float2(o2, o3);
        }
    }
    __syncthreads();

    int ty = tid >> 4, tx = tid & 15;
    float s[8], q[8];
#pragma unroll
    for (int j = 0; j < 8; j++) { s[j] = 0.f; q[j] = 0.f; }
#pragma unroll
    for (int i = 0; i < 8; i++) {
        int row = row0 + ty * 8 + i;
        if (row >= Nn) continue;
#pragma unroll
        for (int j = 0; j < 8; j++) {
            float v = stg[(ty * 8 + i) * 132 + tx * 8 + j];
            s[j] += v;
            q[j] = fmaf(v, v, q[j]);
        }
    }
#pragma unroll
    for (int j = 0; j < 8; j++) {
        atomicAdd(&red[tx * 8 + j], s[j]);
        atomicAdd(&red[128 + tx * 8 + j], q[j]);
    }
    __syncthreads();
    if (tid < 128) atomicAdd(&sS[tid], red[tid]);
    else           atomicAdd(&sQ[tid - 128], red[tid]);
}

// =====================================================================
// lin1 GEMM via mma.sync bf16 split (R10 winner, unchanged)
// =====================================================================
#define LMA_STAGE 0
#define LMA_RED   67584
#define LMA_PMAX  68608
#define LMA_PMIN  70656
#define LMA_SMEM  72704

__global__ __launch_bounds__(256) void k_gemm_lin_mma(const float* __restrict__ A,
                                                      const float* __restrict__ bias,
                                                      const int* __restrict__ batch,
                                                      float* __restrict__ sS,
                                                      float* __restrict__ sQ) {
    extern __shared__ char smem[];
    __shared__ float sbn_sc[256], sbn_sh[256];
    unsigned int sb = smem_u32(smem);
    int tid = threadIdx.x;
    int lane = tid & 31;
    int wid = tid >> 5;
    int warp_m = wid & 3;
    int warp_n = wid >> 2;
    int row0 = blockIdx.x * 128;
    int col0 = blockIdx.y * 128;
    sbn_sc[tid] = g_bnsc[tid];
    sbn_sh[tid] = g_bnsh[tid];
    __syncthreads();

    float acc[2][8][4];
#pragma unroll
    for (int mt = 0; mt < 2; mt++)
#pragma unroll
        for (int nt = 0; nt < 8; nt++)
#pragma unroll
            for (int j = 0; j < 4; j++) acc[mt][nt][j] = 0.f;

    int col4 = tid & 15;
    int rbase = tid >> 4;

    for (int c = 0; c < 4; c++) {
        int kbase = c * 64;
#pragma unroll
        for (int i = 0; i < 8; i++) {
            int r = rbase + i * 16;
            int grow = row0 + r;
            float4 v = make_float4(0.f, 0.f, 0.f, 0.f);
            if (grow < Nn) {
                v = *reinterpret_cast<const float4*>(&A[(size_t)grow * 256 + kbase + col4 * 4]);
                int kc = kbase + col4 * 4;
                v.x = fmaf(v.x, sbn_sc[kc],     sbn_sh[kc]);
                v.y = fmaf(v.y, sbn_sc[kc + 1], sbn_sh[kc + 1]);
                v.z = fmaf(v.z, sbn_sc[kc + 2], sbn_sh[kc + 2]);
                v.w = fmaf(v.w, sbn_sc[kc + 3], sbn_sh[kc + 3]);
            }
            unsigned short h0, l0, h1, l1, h2, l2, h3, l3;
            cvt_hilo(v.x, h0, l0);
            cvt_hilo(v.y, h1, l1);
            cvt_hilo(v.z, h2, l2);
            cvt_hilo(v.w, h3, l3);
            int ob = r * 144 + col4 * 8;
            *reinterpret_cast<uint2*>(smem + MMA_A_HI + ob) =
                make_uint2((unsigned)h0 | ((unsigned)h1 << 16), (unsigned)h2 | ((unsigned)h3 << 16));
            *reinterpret_cast<uint2*>(smem + MMA_A_LO + ob) =
                make_uint2((unsigned)l0 | ((unsigned)l1 << 16), (unsigned)l2 | ((unsigned)l3 << 16));
        }
#pragma unroll
        for (int j = 0; j < 4; j++) {
            int idx = tid + j * 256;
            int kr = idx >> 4, c8 = idx & 15;
            int ob = kr * 272 + c8 * 16;
            *reinterpret_cast<uint4*>(smem + MMA_B_HI + ob) =
                *reinterpret_cast<const uint4*>(&g_Wlbh[(kbase + kr) * 256 + col0 + c8 * 8]);
            *reinterpret_cast<uint4*>(smem + MMA_B_LO + ob) =
                *reinterpret_cast<const uint4*>(&g_Wlbl[(kbase + kr) * 256 + col0 + c8 * 8]);
        }
        __syncthreads();

#pragma unroll
        for (int ks = 0; ks < 4; ks++) {
            unsigned int Ah[2][4], Al[2][4], Bf[4][4];
            int arow = (lane & 15);
            int acolb = ks * 32 + (lane >> 4) * 16;
#pragma unroll
            for (int mt = 0; mt < 2; mt++) {
                int m0 = warp_m * 32 + mt * 16;
                unsigned int aoff = (unsigned)((m0 + arow) * 144 + acolb);
                ldm_x4(Ah[mt], sb + MMA_A_HI + aoff);
                ldm_x4(Al[mt], sb + MMA_A_LO + aoff);
            }
            int brow = ks * 16 + (lane & 15);
#pragma unroll
            for (int p = 0; p < 4; p++) {
                unsigned int boff = (unsigned)(brow * 272 + (warp_n * 64 + p * 16 + (lane >> 4) * 8) * 2);
                ldm_x4t(Bf[p], sb + MMA_B_HI + boff);
            }
#pragma unroll
            for (int mt = 0; mt < 2; mt++)
#pragma unroll
                for (int p = 0; p < 4; p++) {
                    mma_bf16(acc[mt][2 * p],     Ah[mt], &Bf[p][0]);
                    mma_bf16(acc[mt][2 * p + 1], Ah[mt], &Bf[p][2]);
                    mma_bf16(acc[mt][2 * p],     Al[mt], &Bf[p][0]);
                    mma_bf16(acc[mt][2 * p + 1], Al[mt], &Bf[p][2]);
                }
#pragma unroll
            for (int p = 0; p < 4; p++) {
                unsigned int boff = (unsigned)(brow * 272 + (warp_n * 64 + p * 16 + (lane >> 4) * 8) * 2);
                ldm_x4t(Bf[p], sb + MMA_B_LO + boff);
            }
#pragma unroll
            for (int mt = 0; mt < 2; mt++)
#pragma unroll
                for (int p = 0; p < 4; p++) {
                    mma_bf16(acc[mt][2 * p],     Ah[mt], &Bf[p][0]);
                    mma_bf16(acc[mt][2 * p + 1], Ah[mt], &Bf[p][2]);
                }
        }
        __syncthreads();
    }

    float* stg = reinterpret_cast<float*>(smem + LMA_STAGE);
#pragma unroll
    for (int mt = 0; mt < 2; mt++) {
        int rloc = warp_m * 32 + mt * 16 + (lane >> 2);
#pragma unroll
        for (int nt = 0; nt < 8; nt++) {
            int cloc = warp_n * 64 + nt * 8 + (lane & 3) * 2;
            float b0 = __ldg(&bias[col0 + cloc]), b1 = __ldg(&bias[col0 + cloc + 1]);
            stg[rloc * 132 + cloc]           = fmaxf(acc[mt][nt][0] + b0, 0.f);
            stg[rloc * 132 + cloc + 1]       = fmaxf(acc[mt][nt][1] + b1, 0.f);
            stg[(rloc + 8) * 132 + cloc]     = fmaxf(acc[mt][nt][2] + b0, 0.f);
            stg[(rloc + 8) * 132 + cloc + 1] = fmaxf(acc[mt][nt][3] + b1, 0.f);
        }
    }
    float* red  = reinterpret_cast<float*>(smem + LMA_RED);
    int*  pmaxS = reinterpret_cast<int*>(smem + LMA_PMAX);
    int*  pminS = reinterpret_cast<int*>(smem + LMA_PMIN);
    red[tid] = 0.f;
    pmaxS[tid] = 0; pmaxS[tid + 256] = 0;
    pminS[tid] = 0x7F800000; pminS[tid + 256] = 0x7F800000;
    __syncthreads();

    int ty = tid >> 4, tx = tid & 15;
    int gbase = batch[row0];
    float s[8], q[8], vmx[8], vmn[8];
#pragma unroll
    for (int j = 0; j < 8; j++) { s[j] = 0.f; q[j] = 0.f; vmx[j] = 0.f; vmn[j] = __int_as_float(0x7F800000); }
    int cur_slot = -1;
#pragma unroll
    for (int i = 0; i < 8; i++) {
        int row = row0 + ty * 8 + i;
        if (row >= Nn) continue;
        int slot = batch[row] - gbase;
        if (slot != cur_slot) {
            if (cur_slot >= 0) {
#pragma unroll
                for (int j = 0; j < 8; j++) {
                    int c = tx * 8 + j;
                    if (cur_slot < 4) {
                        atomicMax(&pmaxS[cur_slot * 128 + c], __float_as_int(vmx[j]));
                        atomicMin(&pminS[cur_slot * 128 + c], __float_as_int(vmn[j]));
                    } else {
                        atomicMax(&g_pmax[(gbase + cur_slot) * 256 + col0 + c], __float_as_int(vmx[j]));
                        atomicMin(&g_pmin[(gbase + cur_slot) * 256 + col0 + c], __float_as_int(vmn[j]));
                    }
                    vmx[j] = 0.f; vmn[j] = __int_as_float(0x7F800000);
                }
            }
            cur_slot = slot;
        }
#pragma unroll
        for (int j = 0; j < 8; j++) {
            float v = stg[(ty * 8 + i) * 132 + tx * 8 + j];
            s[j] += v;
            q[j] = fmaf(v, v, q[j]);
            vmx[j] = fmaxf(vmx[j], v);
            vmn[j] = fminf(vmn[j], v);
        }
    }
    if (cur_slot >= 0) {
#pragma unroll
        for (int j = 0; j < 8; j++) {
            int c = tx * 8 + j;
            if (cur_slot < 4) {
                atomicMax(&pmaxS[cur_slot * 128 + c], __float_as_int(vmx[j]));
                atomicMin(&pminS[cur_slot * 128 + c], __float_as_int(vmn[j]));
            } else {
                atomicMax(&g_pmax[(gbase + cur_slot) * 256 + col0 + c], __float_as_int(vmx[j]));
                atomicMin(&g_pmin[(gbase + cur_slot) * 256 + col0 + c], __float_as_int(vmn[j]));
            }
        }
    }
#pragma unroll
    for (int j = 0; j < 8; j++) {
        atomicAdd(&red[tx * 8 + j], s[j]);
        atomicAdd(&red[128 + tx * 8 + j], q[j]);
    }
    __syncthreads();
    if (tid < 128) {
        atomicAdd(&sS[col0 + tid], red[tid]);
#pragma unroll
        for (int sl = 0; sl < 4; sl++) {
            int g = gbase + sl;
            if (g < Gg) {
                atomicMax(&g_pmax[g * 256 + col0 + tid], pmaxS[sl * 128 + tid]);
                atomicMin(&g_pmin[g * 256 + col0 + tid], pminS[sl * 128 + tid]);
            }
        }
    } else {
        atomicAdd(&sQ[col0 + tid - 128], red[tid]);
    }
}

// ---------------- BN stats / params / pooled BN ----------------
__global__ __launch_bounds__(128) void k_colstats(const float* __restrict__ X, int ldx,
                                                  float* __restrict__ stats) {
    int c = threadIdx.x;
    int Cch = blockDim.x;
    int r0 = blockIdx.x * 256;
    int r1 = min(r0 + 256, Nn);
    float s = 0.f, q = 0.f;
    for (int r = r0; r < r1; r++) {
        float v = X[(size_t)r * ldx + c];
        s += v;
        q = fmaf(v, v, q);
    }
    atomicAdd(&stats[c], s);
    atomicAdd(&stats[Cch + c], q);
}

__global__ __launch_bounds__(128) void k_bnparam(const float* __restrict__ sS,
                                                 const float* __restrict__ sQ,
                                                 const float* __restrict__ gamma,
                                                 const float* __restrict__ beta,
                                                 float* __restrict__ osc,
                                                 float* __restrict__ osh) {
    int c = threadIdx.x;
    float m = sS[c] * (1.f / Nn);
    float var = sQ[c] * (1.f / Nn) - m * m;
    float sc = gamma[c] * rsqrtf(var + EPSb);
    osc[c] = sc;
    osh[c] = beta[c] - m * sc;
}

__global__ __launch_bounds__(256) void k_poolbn(const float* __restrict__ gammal,
                                                const float* __restrict__ betal) {
    int c = threadIdx.x;
    int g = blockIdx.x;
    float m = g_stats[512 + c] * (1.f / Nn);
    float var = g_stats[768 + c] * (1.f / Nn) - m * m;
    float sc = gammal[c] * rsqrtf(var + EPSb);
    float sh = betal[c] - m * sc;
    float vmax = __int_as_float(g_pmax[g * 256 + c]);
    float vmin = __int_as_float(g_pmin[g * 256 + c]);
    g_pooled[g * 256 + c] = (sc >= 0.f ? sc * vmax : sc * vmin) + sh;
}

// ---------------- head ----------------
__global__ __launch_bounds__(128) void k_head_gemm_relu(const float* __restrict__ A,
                                                        const float* __restrict__ B,
                                                        const float* __restrict__ bias,
                                                        float* __restrict__ Cmat,
                                                        int Kd, int Nc) {
    int idx = blockIdx.x * blockDim.x + threadIdx.x;
    if (idx >= Gg * Nc) return;
    int g = idx / Nc, c = idx - g * Nc;
    float acc = bias[c];
    for (int k = 0; k < Kd; k++) acc = fmaf(A[g * Kd + k], B[k * Nc + c], acc);
    Cmat[idx] = fmaxf(acc, 0.f);
}

__global__ __launch_bounds__(256) void k_head_bn(float* __restrict__ X,
                                                 const float* __restrict__ gamma,
                                                 const float* __restrict__ beta, int Cch) {
    int c = threadIdx.x;
    if (c >= Cch) return;
    float s = 0.f, q = 0.f;
    for (int g = 0; g < Gg; g++) {
        float v = X[g * Cch + c];
        s += v;
        q += v * v;
    }
    float m = s / Gg;
    float var = q / Gg - m * m;
    float sc = gamma[c] * rsqrtf(var + EPSb);
    float sh = beta[c] - m * sc;
    for (int g = 0; g < Gg; g++) X[g * Cch + c] = X[g * Cch + c] * sc + sh;
}

__global__ __launch_bounds__(64) void k_logits(const float* __restrict__ Wf3,
                                               const float* __restrict__ bf3,
                                               float* __restrict__ out) {
    int g = blockIdx.x;
    int c = threadIdx.x;
    __shared__ float sl[64];
    __shared__ float s_m, s_l;
    float v = -INFINITY;
    if (c < Cc) {
        float acc = bf3[c];
        for (int k = 0; k < 128; k++) acc = fmaf(g_f2[g * 128 + k], Wf3[k * Cc + c], acc);
        v = acc;
    }
    sl[c] = v;
    __syncthreads();
    if (c == 0) {
        float m = -INFINITY;
        for (int i = 0; i < Cc; i++) m = fmaxf(m, sl[i]);
        float s = 0.f;
        for (int i = 0; i < Cc; i++) s += expf(sl[i] - m);
        s_m = m;
        s_l = logf(s);
    }
    __syncthreads();
    if (c < Cc) out[g * Cc + c] = sl[c] - s_m - s_l;
}

// ---------------- launch ----------------
extern "C" void kernel_launch(void* const* d_in, const int* in_sizes, int n_in,
                              void* d_out, int out_size) {
    const float* x      = (const float*)d_in[0];
    const int*   ei     = (const int*)d_in[1];
    const float* ea     = (const float*)d_in[2];
    const int*   batch  = (const int*)d_in[3];
    const float* W1     = (const float*)d_in[4];
    const float* b1     = (const float*)d_in[5];
    const float* gamma1 = (const float*)d_in[6];
    const float* beta1  = (const float*)d_in[7];
    const float* W2     = (const float*)d_in[8];
    const float* b2     = (const float*)d_in[9];
    const float* gamma2 = (const float*)d_in[10];
    const float* beta2  = (const float*)d_in[11];
    const float* Wl     = (const float*)d_in[12];
    const float* bl     = (const float*)d_in[13];
    const float* gammal = (const float*)d_in[14];
    const float* betal  = (const float*)d_in[15];
    const float* Wf1    = (const float*)d_in[16];
    const float* bf1    = (const float*)d_in[17];
    const float* gammaf1= (const float*)d_in[18];
    const float* betaf1 = (const float*)d_in[19];
    const float* Wf2    = (const float*)d_in[20];
    const float* bf2    = (const float*)d_in[21];
    const float* gammaf2= (const float*)d_in[22];
    const float* betaf2 = (const float*)d_in[23];
    const float* Wf3    = (const float*)d_in[24];
    const float* bf3    = (const float*)d_in[25];
    const int* row = ei;
    const int* col = ei + Ee;
    float* out = (float*)d_out;

    float *p_hcat1, *p_hcat2, *p_xcat, *p_stats, *p_pooled, *p_f1, *p_f2, *p_deg, *p_bnsc, *p_bnsh;
    int *p_cnt, *p_cur, *p_pmax, *p_pmin;
    unsigned short *p_W2bh, *p_W2bl, *p_Wlbh, *p_Wlbl, *p_W1bh, *p_W1bl;
    cudaGetSymbolAddress((void**)&p_hcat1, g_hcat1);
    cudaGetSymbolAddress((void**)&p_hcat2, g_hcat2);
    cudaGetSymbolAddress((void**)&p_xcat, g_xcat);
    cudaGetSymbolAddress((void**)&p_stats, g_stats);
    cudaGetSymbolAddress((void**)&p_pooled, g_pooled);
    cudaGetSymbolAddress((void**)&p_f1, g_f1);
    cudaGetSymbolAddress((void**)&p_f2, g_f2);
    cudaGetSymbolAddress((void**)&p_deg, g_deg);
    cudaGetSymbolAddress((void**)&p_bnsc, g_bnsc);
    cudaGetSymbolAddress((void**)&p_bnsh, g_bnsh);
    cudaGetSymbolAddress((void**)&p_cnt, g_cnt);
    cudaGetSymbolAddress((void**)&p_cur, g_cur);
    cudaGetSymbolAddress((void**)&p_pmax, g_pmax);
    cudaGetSymbolAddress((void**)&p_pmin, g_pmin);
    cudaGetSymbolAddress((void**)&p_W2bh, g_W2bh);
    cudaGetSymbolAddress((void**)&p_W2bl, g_W2bl);
    cudaGetSymbolAddress((void**)&p_Wlbh, g_Wlbh);
    cudaGetSymbolAddress((void**)&p_Wlbl, g_Wlbl);
    cudaGetSymbolAddress((void**)&p_W1bh, g_W1bh);
    cudaGetSymbolAddress((void**)&p_W1bl, g_W1bl);

    cudaFuncSetAttribute(k_gemm_conv2_mma, cudaFuncAttributeMaxDynamicSharedMemorySize,
                         MMA_SMEM);
    cudaFuncSetAttribute(k_gemm_conv1_mma, cudaFuncAttributeMaxDynamicSharedMemorySize,
                         CMA_SMEM);
    cudaFuncSetAttribute(k_gemm_lin_mma, cudaFuncAttributeMaxDynamicSharedMemorySize,
                         LMA_SMEM);

    cudaMemsetAsync(p_deg, 0, Nn * sizeof(float));
    cudaMemsetAsync(p_cnt, 0, Nn * sizeof(int));
    cudaMemsetAsync(p_cur, 0, Nn * sizeof(int));
    cudaMemsetAsync(p_stats, 0, 1024 * sizeof(float));
    cudaMemsetAsync(p_pmax, 0, Gg * 256 * sizeof(int));
    cudaMemsetAsync(p_pmin, 0x7F, Gg * 256 * sizeof(int));

    k_deg_hist<<<(Ee + 255) / 256, 256>>>(col, ea);
    k_scan<<<1, 256>>>();
    k_scatter<<<(Ee + 255) / 256, 256>>>(row, col, ea);
    k_prepWbf<<<(512 * 128 + 255) / 256, 256>>>(W2, p_W2bh, p_W2bl, 512 * 128);
    k_prepWbf<<<(256 * 256 + 255) / 256, 256>>>(Wl, p_Wlbh, p_Wlbl, 256 * 256);
    k_prepWbf<<<(64 * 128 + 255) / 256, 256>>>(W1, p_W1bh, p_W1bl, 64 * 128);

    // conv1: hop1 gathers from x; GEMM reads x (cols 0-15) + hcat1 (h1..h3)
    k_prop_x<4, false><<<(Nn * 4 + 255) / 256, 256>>>(x, 16, p_hcat1, 48, nullptr, nullptr);
    k_prop<4><<<(Nn * 4 + 255) / 256, 256>>>(p_hcat1, 48, 0, 16);
    k_prop<4><<<(Nn * 4 + 255) / 256, 256>>>(p_hcat1, 48, 16, 32);
    k_gemm_conv1_mma<<<(Nn + 127) / 128, 256, CMA_SMEM>>>(x, p_hcat1, b1, p_xcat,
                                                          p_stats, p_stats + 128);
    k_bnparam<<<1, 128>>>(p_stats, p_stats + 128, gamma1, beta1, p_bnsc, p_bnsh);

    // conv2: hop1 gathers from xcat (algebraic BN); GEMM reads xcat (BN) + hcat2
    k_prop_x<32, true><<<(Nn * 32 + 255) / 256, 256>>>(p_xcat, 256, p_hcat2, 384,
                                                       p_bnsc, p_bnsh);
    k_prop<32><<<(Nn * 32 + 255) / 256, 256>>>(p_hcat2, 384, 0, 128);
    k_prop<32><<<(Nn * 32 + 255) / 256, 256>>>(p_hcat2, 384, 128, 256);
    k_gemm_conv2_mma<<<(Nn + 127) / 128, 256, MMA_SMEM>>>(p_xcat, p_hcat2, b2, p_xcat + 128);
    k_colstats<<<(Nn + 255) / 256, 128>>>(p_xcat + 128, 256, p_stats + 256);
    k_bnparam<<<1, 128>>>(p_stats + 256, p_stats + 384, gamma2, beta2, p_bnsc + 128, p_bnsh + 128);

    // lin1 (mma bf16-split, BN-at-load + fused stats+pool)
    dim3 glin((Nn + 127) / 128, 2);
    k_gemm_lin_mma<<<glin, 256, LMA_SMEM>>>(p_xcat, bl, batch, p_stats + 512, p_stats + 768);
    k_poolbn<<<Gg, 256>>>(gammal, betal);

    // head
    k_head_gemm_relu<<<(Gg * 256 + 127) / 128, 128>>>(p_pooled, Wf1, bf1, p_f1, 256, 256);
    k_head_bn<<<1, 256>>>(p_f1, gammaf1, betaf1, 256);
    k_head_gemm_relu<<<(Gg * 128 + 127) / 128, 128>>>(p_f1, Wf2, bf2, p_f2, 256, 128);
    k_head_bn<<<1, 128>>>(p_f2, gammaf2, betaf2, 128);
    k_logits<<<Gg, 64>>>(Wf3, bf3, out);
}

// round 15
// speedup vs baseline: 1.0275x; 1.0275x over previous
#include <cuda_runtime.h>
#include <cuda_bf16.h>
#include <math.h>

#define Nn 100000
#define Ee 1600000
#define Gg 64
#define Cc 40
#define EPSb 1e-5f

// ---------------- scratch ----------------
__device__ __align__(128) float g_deg[Nn];
__device__ __align__(128) int   g_cnt[Nn];
__device__ __align__(128) int   g_off[Nn];
__device__ __align__(128) int   g_cur[Nn];
__device__ __align__(128) int   g_rowS[Ee];
__device__ __align__(128) float g_wS[Ee];
__device__ __align__(128) float g_hcat1[Nn * 64];
__device__ __align__(128) float g_hcat2[(size_t)Nn * 512];
__device__ __align__(128) float g_xcat[(size_t)Nn * 256];
__device__ __align__(128) float g_stats[1024];
__device__ __align__(128) float g_bnsc[256];
__device__ __align__(128) float g_bnsh[256];
__device__ __align__(128) int   g_pmax[Gg * 256];
__device__ __align__(128) int   g_pmin[Gg * 256];
__device__ __align__(128) float g_pooled[Gg * 256];
__device__ __align__(128) float g_f1[Gg * 256];
__device__ __align__(128) float g_f2[Gg * 128];
__device__ __align__(128) unsigned short g_W2bh[512 * 128];
__device__ __align__(128) unsigned short g_W2bl[512 * 128];
__device__ __align__(128) unsigned short g_Wlbh[256 * 256];
__device__ __align__(128) unsigned short g_Wlbl[256 * 256];
__device__ __align__(128) unsigned short g_W1bh[64 * 128];
__device__ __align__(128) unsigned short g_W1bl[64 * 128];

// ---------------- helpers ----------------
__device__ __forceinline__ unsigned int smem_u32(const void* p) {
    unsigned int a;
    asm("{ .reg .u64 t; cvta.to.shared.u64 t, %1; cvt.u32.u64 %0, t; }" : "=r"(a) : "l"(p));
    return a;
}
__device__ __forceinline__ void cvt_hilo(float a, unsigned short& h, unsigned short& l) {
    __nv_bfloat16 bh = __float2bfloat16(a);
    float r = a - __bfloat162float(bh);
    __nv_bfloat16 bl = __float2bfloat16(r);
    h = __bfloat16_as_ushort(bh);
    l = __bfloat16_as_ushort(bl);
}
__device__ __forceinline__ void ldm_x4(unsigned int* r, unsigned int addr) {
    asm volatile("ldmatrix.sync.aligned.m8n8.x4.shared.b16 {%0,%1,%2,%3}, [%4];"
                 : "=r"(r[0]), "=r"(r[1]), "=r"(r[2]), "=r"(r[3]) : "r"(addr));
}
__device__ __forceinline__ void ldm_x4t(unsigned int* r, unsigned int addr) {
    asm volatile("ldmatrix.sync.aligned.m8n8.x4.trans.shared.b16 {%0,%1,%2,%3}, [%4];"
                 : "=r"(r[0]), "=r"(r[1]), "=r"(r[2]), "=r"(r[3]) : "r"(addr));
}
__device__ __forceinline__ void mma_bf16(float* c, const unsigned int* a, const unsigned int* b) {
    asm volatile(
        "mma.sync.aligned.m16n8k16.row.col.f32.bf16.bf16.f32 "
        "{%0,%1,%2,%3}, {%4,%5,%6,%7}, {%8,%9}, {%0,%1,%2,%3};"
        : "+f"(c[0]), "+f"(c[1]), "+f"(c[2]), "+f"(c[3])
        : "r"(a[0]), "r"(a[1]), "r"(a[2]), "r"(a[3]), "r"(b[0]), "r"(b[1]));
}

// ---------------- graph preprocessing ----------------
__global__ __launch_bounds__(256) void k_deg_hist(const int* __restrict__ col,
                                                  const float* __restrict__ ea) {
    int e = blockIdx.x * blockDim.x + threadIdx.x;
    if (e >= Ee) return;
    int c = col[e];
    atomicAdd(&g_deg[c], ea[e]);
    atomicAdd(&g_cnt[c], 1);
}

__global__ __launch_bounds__(256) void k_scan() {
    __shared__ int ss[256];
    const int CH = (Nn + 255) / 256;
    int t = threadIdx.x;
    int base = t * CH;
    int s = 0;
    for (int i = 0; i < CH; i++) { int idx = base + i; if (idx < Nn) s += g_cnt[idx]; }
    ss[t] = s;
    __syncthreads();
    int own = s;
    for (int o = 1; o < 256; o <<= 1) {
        int v = (t >= o) ? ss[t - o] : 0;
        __syncthreads();
        ss[t] += v;
        __syncthreads();
    }
    int run = ss[t] - own;
    for (int i = 0; i < CH; i++) {
        int idx = base + i;
        if (idx < Nn) { g_off[idx] = run; run += g_cnt[idx]; }
    }
}

__global__ __launch_bounds__(256) void k_scatter(const int* __restrict__ row,
                                                 const int* __restrict__ col,
                                                 const float* __restrict__ ea) {
    int e = blockIdx.x * blockDim.x + threadIdx.x;
    if (e >= Ee) return;
    int r = row[e], c = col[e];
    float dr = g_deg[r], dc = g_deg[c];
    float ir = dr > 0.f ? rsqrtf(dr) : 0.f;
    float ic = dc > 0.f ? rsqrtf(dc) : 0.f;
    float w = ir * ea[e] * ic;
    int p = g_off[c] + atomicAdd(&g_cur[c], 1);
    g_rowS[p] = r;
    g_wS[p] = w;
}

__global__ __launch_bounds__(256) void k_copyx(const float* __restrict__ x) {
    int i = blockIdx.x * blockDim.x + threadIdx.x;
    if (i >= Nn * 16) return;
    int n = i >> 4, j = i & 15;
    g_hcat1[n * 64 + j] = x[i];
}

// CSR gather propagation
template <int TPN>
__global__ __launch_bounds__(256) void k_prop(float* __restrict__ hbase, int stride,
                                              int so, int dofs) {
    int gid = blockIdx.x * blockDim.x + threadIdx.x;
    int node = gid / TPN;
    int part = gid % TPN;
    if (node >= Nn) return;
    int s = g_off[node];
    int e = s + g_cnt[node];
    float4 acc = make_float4(0.f, 0.f, 0.f, 0.f);
    int so4 = so + part * 4;
    for (int i = s; i < e; i++) {
        int r = __ldg(&g_rowS[i]);
        float w = __ldg(&g_wS[i]);
        const float4 v = *reinterpret_cast<const float4*>(hbase + (size_t)r * stride + so4);
        acc.x = fmaf(w, v.x, acc.x);
        acc.y = fmaf(w, v.y, acc.y);
        acc.z = fmaf(w, v.z, acc.z);
        acc.w = fmaf(w, v.w, acc.w);
    }
    *reinterpret_cast<float4*>(hbase + (size_t)node * stride + dofs + part * 4) = acc;
}

// ---------------- weights -> bf16 hi/lo images ----------------
__global__ __launch_bounds__(256) void k_prepWbf(const float* __restrict__ W,
                                                 unsigned short* __restrict__ oh,
                                                 unsigned short* __restrict__ ol, int n) {
    int idx = blockIdx.x * blockDim.x + threadIdx.x;
    if (idx >= n) return;
    unsigned short h, l;
    cvt_hilo(W[idx], h, l);
    oh[idx] = h;
    ol[idx] = l;
}

// =====================================================================
// shared smem layout constants for mma kernels
// =====================================================================
#define MMA_A_HI 0
#define MMA_A_LO 18432
#define MMA_B_HI 36864
#define MMA_B_LO 54272
#define MMA_SMEM 71680
#define STG_RED  67584   // 256 floats after 128x132 fp32 staging

// =====================================================================
// conv2 GEMM via mma.sync bf16 split + staged-stats epilogue (proven
// conv1/lin pattern: stage relu into smem, then 8x8 column reduction).
// =====================================================================
__global__ __launch_bounds__(256) void k_gemm_conv2_mma(const float* __restrict__ A,
                                                        const float* __restrict__ bias,
                                                        float* __restrict__ C,
                                                        float* __restrict__ sS,
                                                        float* __restrict__ sQ) {
    extern __shared__ char smem[];
    unsigned int sb = smem_u32(smem);
    int tid = threadIdx.x;
    int lane = tid & 31;
    int wid = tid >> 5;
    int warp_m = wid & 3;
    int warp_n = wid >> 2;
    int row0 = blockIdx.x * 128;

    float acc[2][8][4];
#pragma unroll
    for (int mt = 0; mt < 2; mt++)
#pragma unroll
        for (int nt = 0; nt < 8; nt++)
#pragma unroll
            for (int j = 0; j < 4; j++) acc[mt][nt][j] = 0.f;

    int col4 = tid & 15;
    int rbase = tid >> 4;

    for (int c = 0; c < 8; c++) {
        int kbase = c * 64;
#pragma unroll
        for (int i = 0; i < 8; i++) {
            int r = rbase + i * 16;
            int grow = row0 + r;
            float4 v = make_float4(0.f, 0.f, 0.f, 0.f);
            if (grow < Nn)
                v = *reinterpret_cast<const float4*>(&A[(size_t)grow * 512 + kbase + col4 * 4]);
            unsigned short h0, l0, h1, l1, h2, l2, h3, l3;
            cvt_hilo(v.x, h0, l0);
            cvt_hilo(v.y, h1, l1);
            cvt_hilo(v.z, h2, l2);
            cvt_hilo(v.w, h3, l3);
            int ob = r * 144 + col4 * 8;
            *reinterpret_cast<uint2*>(smem + MMA_A_HI + ob) =
                make_uint2((unsigned)h0 | ((unsigned)h1 << 16), (unsigned)h2 | ((unsigned)h3 << 16));
            *reinterpret_cast<uint2*>(smem + MMA_A_LO + ob) =
                make_uint2((unsigned)l0 | ((unsigned)l1 << 16), (unsigned)l2 | ((unsigned)l3 << 16));
        }
#pragma unroll
        for (int j = 0; j < 4; j++) {
            int idx = tid + j * 256;
            int kr = idx >> 4, c8 = idx & 15;
            int ob = kr * 272 + c8 * 16;
            *reinterpret_cast<uint4*>(smem + MMA_B_HI + ob) =
                *reinterpret_cast<const uint4*>(&g_W2bh[(kbase + kr) * 128 + c8 * 8]);
            *reinterpret_cast<uint4*>(smem + MMA_B_LO + ob) =
                *reinterpret_cast<const uint4*>(&g_W2bl[(kbase + kr) * 128 + c8 * 8]);
        }
        __syncthreads();

#pragma unroll
        for (int ks = 0; ks < 4; ks++) {
            unsigned int Ah[2][4], Al[2][4], Bf[4][4];
            int arow = (lane & 15);
            int acolb = ks * 32 + (lane >> 4) * 16;
#pragma unroll
            for (int mt = 0; mt < 2; mt++) {
                int m0 = warp_m * 32 + mt * 16;
                unsigned int aoff = (unsigned)((m0 + arow) * 144 + acolb);
                ldm_x4(Ah[mt], sb + MMA_A_HI + aoff);
                ldm_x4(Al[mt], sb + MMA_A_LO + aoff);
            }
            int brow = ks * 16 + (lane & 15);
#pragma unroll
            for (int p = 0; p < 4; p++) {
                unsigned int boff = (unsigned)(brow * 272 + (warp_n * 64 + p * 16 + (lane >> 4) * 8) * 2);
                ldm_x4t(Bf[p], sb + MMA_B_HI + boff);
            }
#pragma unroll
            for (int mt = 0; mt < 2; mt++)
#pragma unroll
                for (int p = 0; p < 4; p++) {
                    mma_bf16(acc[mt][2 * p],     Ah[mt], &Bf[p][0]);
                    mma_bf16(acc[mt][2 * p + 1], Ah[mt], &Bf[p][2]);
                    mma_bf16(acc[mt][2 * p],     Al[mt], &Bf[p][0]);
                    mma_bf16(acc[mt][2 * p + 1], Al[mt], &Bf[p][2]);
                }
#pragma unroll
            for (int p = 0; p < 4; p++) {
                unsigned int boff = (unsigned)(brow * 272 + (warp_n * 64 + p * 16 + (lane >> 4) * 8) * 2);
                ldm_x4t(Bf[p], sb + MMA_B_LO + boff);
            }
#pragma unroll
            for (int mt = 0; mt < 2; mt++)
#pragma unroll
                for (int p = 0; p < 4; p++) {
                    mma_bf16(acc[mt][2 * p],     Ah[mt], &Bf[p][0]);
                    mma_bf16(acc[mt][2 * p + 1], Ah[mt], &Bf[p][2]);
                }
        }
        __syncthreads();
    }

    // ---- stage relu(bias+acc) into smem [128][132] + store to C ----
    float* stg = reinterpret_cast<float*>(smem);
    float* red = reinterpret_cast<float*>(smem + STG_RED);
    red[tid] = 0.f;
#pragma unroll
    for (int mt = 0; mt < 2; mt++) {
        int rloc = warp_m * 32 + mt * 16 + (lane >> 2);
        int r0 = row0 + rloc;
#pragma unroll
        for (int nt = 0; nt < 8; nt++) {
            int cloc = warp_n * 64 + nt * 8 + (lane & 3) * 2;
            float b0 = __ldg(&bias[cloc]), b1 = __ldg(&bias[cloc + 1]);
            float o0 = fmaxf(acc[mt][nt][0] + b0, 0.f);
            float o1 = fmaxf(acc[mt][nt][1] + b1, 0.f);
            float o2 = fmaxf(acc[mt][nt][2] + b0, 0.f);
            float o3 = fmaxf(acc[mt][nt][3] + b1, 0.f);
            stg[rloc * 132 + cloc]           = o0;
            stg[rloc * 132 + cloc + 1]       = o1;
            stg[(rloc + 8) * 132 + cloc]     = o2;
            stg[(rloc + 8) * 132 + cloc + 1] = o3;
            if (r0 < Nn)
                *reinterpret_cast<float2*>(&C[(size_t)r0 * 256 + cloc]) = make_float2(o0, o1);
            if (r0 + 8 < Nn)
                *reinterpret_cast<float2*>(&C[(size_t)(r0 + 8) * 256 + cloc]) = make_float2(o2, o3);
        }
    }
    __syncthreads();

    // ---- proven stats epilogue from staging ----
    int ty = tid >> 4, tx = tid & 15;
    float s[8], q[8];
#pragma unroll
    for (int j = 0; j < 8; j++) { s[j] = 0.f; q[j] = 0.f; }
#pragma unroll
    for (int i = 0; i < 8; i++) {
        int row = row0 + ty * 8 + i;
        if (row >= Nn) continue;
#pragma unroll
        for (int j = 0; j < 8; j++) {
            float v = stg[(ty * 8 + i) * 132 + tx * 8 + j];
            s[j] += v;
            q[j] = fmaf(v, v, q[j]);
        }
    }
#pragma unroll
    for (int j = 0; j < 8; j++) {
        atomicAdd(&red[tx * 8 + j], s[j]);
        atomicAdd(&red[128 + tx * 8 + j], q[j]);
    }
    __syncthreads();
    if (tid < 128) atomicAdd(&sS[tid], red[tid]);
    else           atomicAdd(&sQ[tid - 128], red[tid]);
}

// =====================================================================
// conv1 GEMM via mma.sync bf16 split, K=64 single chunk, staged-stats
// epilogue (R13 winner, unchanged).
// =====================================================================
#define CMA_RED 67584
#define CMA_SMEM 71680

__global__ __launch_bounds__(256) void k_gemm_conv1_mma(const float* __restrict__ A,
                                                        const float* __restrict__ bias,
                                                        float* __restrict__ C,
                                                        float* __restrict__ sS,
                                                        float* __restrict__ sQ) {
    extern __shared__ char smem[];
    unsigned int sb = smem_u32(smem);
    int tid = threadIdx.x;
    int lane = tid & 31;
    int wid = tid >> 5;
    int warp_m = wid & 3;
    int warp_n = wid >> 2;
    int row0 = blockIdx.x * 128;

    float acc[2][8][4];
#pragma unroll
    for (int mt = 0; mt < 2; mt++)
#pragma unroll
        for (int nt = 0; nt < 8; nt++)
#pragma unroll
            for (int j = 0; j < 4; j++) acc[mt][nt][j] = 0.f;

    int col4 = tid & 15;
    int rbase = tid >> 4;

#pragma unroll
    for (int i = 0; i < 8; i++) {
        int r = rbase + i * 16;
        int grow = row0 + r;
        float4 v = make_float4(0.f, 0.f, 0.f, 0.f);
        if (grow < Nn)
            v = *reinterpret_cast<const float4*>(&A[(size_t)grow * 64 + col4 * 4]);
        unsigned short h0, l0, h1, l1, h2, l2, h3, l3;
        cvt_hilo(v.x, h0, l0);
        cvt_hilo(v.y, h1, l1);
        cvt_hilo(v.z, h2, l2);
        cvt_hilo(v.w, h3, l3);
        int ob = r * 144 + col4 * 8;
        *reinterpret_cast<uint2*>(smem + MMA_A_HI + ob) =
            make_uint2((unsigned)h0 | ((unsigned)h1 << 16), (unsigned)h2 | ((unsigned)h3 << 16));
        *reinterpret_cast<uint2*>(smem + MMA_A_LO + ob) =
            make_uint2((unsigned)l0 | ((unsigned)l1 << 16), (unsigned)l2 | ((unsigned)l3 << 16));
    }
#pragma unroll
    for (int j = 0; j < 4; j++) {
        int idx = tid + j * 256;
        int kr = idx >> 4, c8 = idx & 15;
        int ob = kr * 272 + c8 * 16;
        *reinterpret_cast<uint4*>(smem + MMA_B_HI + ob) =
            *reinterpret_cast<const uint4*>(&g_W1bh[kr * 128 + c8 * 8]);
        *reinterpret_cast<uint4*>(smem + MMA_B_LO + ob) =
            *reinterpret_cast<const uint4*>(&g_W1bl[kr * 128 + c8 * 8]);
    }
    __syncthreads();

#pragma unroll
    for (int ks = 0; ks < 4; ks++) {
        unsigned int Ah[2][4], Al[2][4], Bf[4][4];
        int arow = (lane & 15);
        int acolb = ks * 32 + (lane >> 4) * 16;
#pragma unroll
        for (int mt = 0; mt < 2; mt++) {
            int m0 = warp_m * 32 + mt * 16;
            unsigned int aoff = (unsigned)((m0 + arow) * 144 + acolb);
            ldm_x4(Ah[mt], sb + MMA_A_HI + aoff);
            ldm_x4(Al[mt], sb + MMA_A_LO + aoff);
        }
        int brow = ks * 16 + (lane & 15);
#pragma unroll
        for (int p = 0; p < 4; p++) {
            unsigned int boff = (unsigned)(brow * 272 + (warp_n * 64 + p * 16 + (lane >> 4) * 8) * 2);
            ldm_x4t(Bf[p], sb + MMA_B_HI + boff);
        }
#pragma unroll
        for (int mt = 0; mt < 2; mt++)
#pragma unroll
            for (int p = 0; p < 4; p++) {
                mma_bf16(acc[mt][2 * p],     Ah[mt], &Bf[p][0]);
                mma_bf16(acc[mt][2 * p + 1], Ah[mt], &Bf[p][2]);
                mma_bf16(acc[mt][2 * p],     Al[mt], &Bf[p][0]);
                mma_bf16(acc[mt][2 * p + 1], Al[mt], &Bf[p][2]);
            }
#pragma unroll
        for (int p = 0; p < 4; p++) {
            unsigned int boff = (unsigned)(brow * 272 + (warp_n * 64 + p * 16 + (lane >> 4) * 8) * 2);
            ldm_x4t(Bf[p], sb + MMA_B_LO + boff);
        }
#pragma unroll
        for (int mt = 0; mt < 2; mt++)
#pragma unroll
            for (int p = 0; p < 4; p++) {
                mma_bf16(acc[mt][2 * p],     Ah[mt], &Bf[p][0]);
                mma_bf16(acc[mt][2 * p + 1], Ah[mt], &Bf[p][2]);
            }
    }
    __syncthreads();

    float* stg = reinterpret_cast<float*>(smem);
    float* red = reinterpret_cast<float*>(smem + CMA_RED);
    red[tid] = 0.f;
#pragma unroll
    for (int mt = 0; mt < 2; mt++) {
        int rloc = warp_m * 32 + mt * 16 + (lane >> 2);
        int r0 = row0 + rloc;
#pragma unroll
        for (int nt = 0; nt < 8; nt++) {
            int cloc = warp_n * 64 + nt * 8 + (lane & 3) * 2;
            float b0 = __ldg(&bias[cloc]), b1 = __ldg(&bias[cloc + 1]);
            float o0 = fmaxf(acc[mt][nt][0] + b0, 0.f);
            float o1 = fmaxf(acc[mt][nt][1] + b1, 0.f);
            float o2 = fmaxf(acc[mt][nt][2] + b0, 0.f);
            float o3 = fmaxf(acc[mt][nt][3] + b1, 0.f);
            stg[rloc * 132 + cloc]           = o0;
            stg[rloc * 132 + cloc + 1]       = o1;
            stg[(rloc + 8) * 132 + cloc]     = o2;
            stg[(rloc + 8) * 132 + cloc + 1] = o3;
            if (r0 < Nn)
                *reinterpret_cast<float2*>(&C[(size_t)r0 * 256 + cloc]) = make_float2(o0, o1);
            if (r0 + 8 < Nn)
                *reinterpret_cast<float2*>(&C[(size_t)(r0 + 8) * 256 + cloc]) = make_float2(o2, o3);
        }
    }
    __syncthreads();

    int ty = tid >> 4, tx = tid & 15;
    float s[8], q[8];
#pragma unroll
    for (int j = 0; j < 8; j++) { s[j] = 0.f; q[j] = 0.f; }
#pragma unroll
    for (int i = 0; i < 8; i++) {
        int row = row0 + ty * 8 + i;
        if (row >= Nn) continue;
#pragma unroll
        for (int j = 0; j < 8; j++) {
            float v = stg[(ty * 8 + i) * 132 + tx * 8 + j];
            s[j] += v;
            q[j] = fmaf(v, v, q[j]);
        }
    }
#pragma unroll
    for (int j = 0; j < 8; j++) {
        atomicAdd(&red[tx * 8 + j], s[j]);
        atomicAdd(&red[128 + tx * 8 + j], q[j]);
    }
    __syncthreads();
    if (tid < 128) atomicAdd(&sS[tid], red[tid]);
    else           atomicAdd(&sQ[tid - 128], red[tid]);
}

// =====================================================================
// lin1 GEMM via mma.sync bf16 split (R10 winner, unchanged)
// =====================================================================
#define LMA_STAGE 0
#define LMA_RED   67584
#define LMA_PMAX  68608
#define LMA_PMIN  70656
#define LMA_SMEM  72704

__global__ __launch_bounds__(256) void k_gemm_lin_mma(const float* __restrict__ A,
                                                      const float* __restrict__ bias,
                                                      const int* __restrict__ batch,
                                                      float* __restrict__ sS,
                                                      float* __restrict__ sQ) {
    extern __shared__ char smem[];
    __shared__ float sbn_sc[256], sbn_sh[256];
    unsigned int sb = smem_u32(smem);
    int tid = threadIdx.x;
    int lane = tid & 31;
    int wid = tid >> 5;
    int warp_m = wid & 3;
    int warp_n = wid >> 2;
    int row0 = blockIdx.x * 128;
    int col0 = blockIdx.y * 128;
    sbn_sc[tid] = g_bnsc[tid];
    sbn_sh[tid] = g_bnsh[tid];
    __syncthreads();

    float acc[2][8][4];
#pragma unroll
    for (int mt = 0; mt < 2; mt++)
#pragma unroll
        for (int nt = 0; nt < 8; nt++)
#pragma unroll
            for (int j = 0; j < 4; j++) acc[mt][nt][j] = 0.f;

    int col4 = tid & 15;
    int rbase = tid >> 4;

    for (int c = 0; c < 4; c++) {
        int kbase = c * 64;
#pragma unroll
        for (int i = 0; i < 8; i++) {
            int r = rbase + i * 16;
            int grow = row0 + r;
            float4 v = make_float4(0.f, 0.f, 0.f, 0.f);
            if (grow < Nn) {
                v = *reinterpret_cast<const float4*>(&A[(size_t)grow * 256 + kbase + col4 * 4]);
                int kc = kbase + col4 * 4;
                v.x = fmaf(v.x, sbn_sc[kc],     sbn_sh[kc]);
                v.y = fmaf(v.y, sbn_sc[kc + 1], sbn_sh[kc + 1]);
                v.z = fmaf(v.z, sbn_sc[kc + 2], sbn_sh[kc + 2]);
                v.w = fmaf(v.w, sbn_sc[kc + 3], sbn_sh[kc + 3]);
            }
            unsigned short h0, l0, h1, l1, h2, l2, h3, l3;
            cvt_hilo(v.x, h0, l0);
            cvt_hilo(v.y, h1, l1);
            cvt_hilo(v.z, h2, l2);
            cvt_hilo(v.w, h3, l3);
            int ob = r * 144 + col4 * 8;
            *reinterpret_cast<uint2*>(smem + MMA_A_HI + ob) =
                make_uint2((unsigned)h0 | ((unsigned)h1 << 16), (unsigned)h2 | ((unsigned)h3 << 16));
            *reinterpret_cast<uint2*>(smem + MMA_A_LO + ob) =
                make_uint2((unsigned)l0 | ((unsigned)l1 << 16), (unsigned)l2 | ((unsigned)l3 << 16));
        }
#pragma unroll
        for (int j = 0; j < 4; j++) {
            int idx = tid + j * 256;
            int kr = idx >> 4, c8 = idx & 15;
            int ob = kr * 272 + c8 * 16;
            *reinterpret_cast<uint4*>(smem + MMA_B_HI + ob) =
                *reinterpret_cast<const uint4*>(&g_Wlbh[(kbase + kr) * 256 + col0 + c8 * 8]);
            *reinterpret_cast<uint4*>(smem + MMA_B_LO + ob) =
                *reinterpret_cast<const uint4*>(&g_Wlbl[(kbase + kr) * 256 + col0 + c8 * 8]);
        }
        __syncthreads();

#pragma unroll
        for (int ks = 0; ks < 4; ks++) {
            unsigned int Ah[2][4], Al[2][4], Bf[4][4];
            int arow = (lane & 15);
            int acolb = ks * 32 + (lane >> 4) * 16;
#pragma unroll
            for (int mt = 0; mt < 2; mt++) {
                int m0 = warp_m * 32 + mt * 16;
                unsigned int aoff = (unsigned)((m0 + arow) * 144 + acolb);
                ldm_x4(Ah[mt], sb + MMA_A_HI + aoff);
                ldm_x4(Al[mt], sb + MMA_A_LO + aoff);
            }
            int brow = ks * 16 + (lane & 15);
#pragma unroll
            for (int p = 0; p < 4; p++) {
                unsigned int boff = (unsigned)(brow * 272 + (warp_n * 64 + p * 16 + (lane >> 4) * 8) * 2);
                ldm_x4t(Bf[p], sb + MMA_B_HI + boff);
            }
#pragma unroll
            for (int mt = 0; mt < 2; mt++)
#pragma unroll
                for (int p = 0; p < 4; p++) {
                    mma_bf16(acc[mt][2 * p],     Ah[mt], &Bf[p][0]);
                    mma_bf16(acc[mt][2 * p + 1], Ah[mt], &Bf[p][2]);
                    mma_bf16(acc[mt][2 * p],     Al[mt], &Bf[p][0]);
                    mma_bf16(acc[mt][2 * p + 1], Al[mt], &Bf[p][2]);
                }
#pragma unroll
            for (int p = 0; p < 4; p++) {
                unsigned int boff = (unsigned)(brow * 272 + (warp_n * 64 + p * 16 + (lane >> 4) * 8) * 2);
                ldm_x4t(Bf[p], sb + MMA_B_LO + boff);
            }
#pragma unroll
            for (int mt = 0; mt < 2; mt++)
#pragma unroll
                for (int p = 0; p < 4; p++) {
                    mma_bf16(acc[mt][2 * p],     Ah[mt], &Bf[p][0]);
                    mma_bf16(acc[mt][2 * p + 1], Ah[mt], &Bf[p][2]);
                }
        }
        __syncthreads();
    }

    float* stg = reinterpret_cast<float*>(smem + LMA_STAGE);
#pragma unroll
    for (int mt = 0; mt < 2; mt++) {
        int rloc = warp_m * 32 + mt * 16 + (lane >> 2);
#pragma unroll
        for (int nt = 0; nt < 8; nt++) {
            int cloc = warp_n * 64 + nt * 8 + (lane & 3) * 2;
            float b0 = __ldg(&bias[col0 + cloc]), b1 = __ldg(&bias[col0 + cloc + 1]);
            stg[rloc * 132 + cloc]           = fmaxf(acc[mt][nt][0] + b0, 0.f);
            stg[rloc * 132 + cloc + 1]       = fmaxf(acc[mt][nt][1] + b1, 0.f);
            stg[(rloc + 8) * 132 + cloc]     = fmaxf(acc[mt][nt][2] + b0, 0.f);
            stg[(rloc + 8) * 132 + cloc + 1] = fmaxf(acc[mt][nt][3] + b1, 0.f);
        }
    }
    float* red  = reinterpret_cast<float*>(smem + LMA_RED);
    int*  pmaxS = reinterpret_cast<int*>(smem + LMA_PMAX);
    int*  pminS = reinterpret_cast<int*>(smem + LMA_PMIN);
    red[tid] = 0.f;
    pmaxS[tid] = 0; pmaxS[tid + 256] = 0;
    pminS[tid] = 0x7F800000; pminS[tid + 256] = 0x7F800000;
    __syncthreads();

    int ty = tid >> 4, tx = tid & 15;
    int gbase = batch[row0];
    float s[8], q[8], vmx[8], vmn[8];
#pragma unroll
    for (int j = 0; j < 8; j++) { s[j] = 0.f; q[j] = 0.f; vmx[j] = 0.f; vmn[j] = __int_as_float(0x7F800000); }
    int cur_slot = -1;
#pragma unroll
    for (int i = 0; i < 8; i++) {
        int row = row0 + ty * 8 + i;
        if (row >= Nn) continue;
        int slot = batch[row] - gbase;
        if (slot != cur_slot) {
            if (cur_slot >= 0) {
#pragma unroll
                for (int j = 0; j < 8; j++) {
                    int c = tx * 8 + j;
                    if (cur_slot < 4) {
                        atomicMax(&pmaxS[cur_slot * 128 + c], __float_as_int(vmx[j]));
                        atomicMin(&pminS[cur_slot * 128 + c], __float_as_int(vmn[j]));
                    } else {
                        atomicMax(&g_pmax[(gbase + cur_slot) * 256 + col0 + c], __float_as_int(vmx[j]));
                        atomicMin(&g_pmin[(gbase + cur_slot) * 256 + col0 + c], __float_as_int(vmn[j]));
                    }
                    vmx[j] = 0.f; vmn[j] = __int_as_float(0x7F800000);
                }
            }
            cur_slot = slot;
        }
#pragma unroll
        for (int j = 0; j < 8; j++) {
            float v = stg[(ty * 8 + i) * 132 + tx * 8 + j];
            s[j] += v;
            q[j] = fmaf(v, v, q[j]);
            vmx[j] = fmaxf(vmx[j], v);
            vmn[j] = fminf(vmn[j], v);
        }
    }
    if (cur_slot >= 0) {
#pragma unroll
        for (int j = 0; j < 8; j++) {
            int c = tx * 8 + j;
            if (cur_slot < 4) {
                atomicMax(&pmaxS[cur_slot * 128 + c], __float_as_int(vmx[j]));
                atomicMin(&pminS[cur_slot * 128 + c], __float_as_int(vmn[j]));
            } else {
                atomicMax(&g_pmax[(gbase + cur_slot) * 256 + col0 + c], __float_as_int(vmx[j]));
                atomicMin(&g_pmin[(gbase + cur_slot) * 256 + col0 + c], __float_as_int(vmn[j]));
            }
        }
    }
#pragma unroll
    for (int j = 0; j < 8; j++) {
        atomicAdd(&red[tx * 8 + j], s[j]);
        atomicAdd(&red[128 + tx * 8 + j], q[j]);
    }
    __syncthreads();
    if (tid < 128) {
        atomicAdd(&sS[col0 + tid], red[tid]);
#pragma unroll
        for (int sl = 0; sl < 4; sl++) {
            int g = gbase + sl;
            if (g < Gg) {
                atomicMax(&g_pmax[g * 256 + col0 + tid], pmaxS[sl * 128 + tid]);
                atomicMin(&g_pmin[g * 256 + col0 + tid], pminS[sl * 128 + tid]);
            }
        }
    } else {
        atomicAdd(&sQ[col0 + tid - 128], red[tid]);
    }
}

// ---------------- BN params / h0 / pooled BN ----------------
__global__ __launch_bounds__(128) void k_bnparam(const float* __restrict__ sS,
                                                 const float* __restrict__ sQ,
                                                 const float* __restrict__ gamma,
                                                 const float* __restrict__ beta,
                                                 float* __restrict__ osc,
                                                 float* __restrict__ osh) {
    int c = threadIdx.x;
    float m = sS[c] * (1.f / Nn);
    float var = sQ[c] * (1.f / Nn) - m * m;
    float sc = gamma[c] * rsqrtf(var + EPSb);
    osc[c] = sc;
    osh[c] = beta[c] - m * sc;
}

__global__ __launch_bounds__(256) void k_h0() {
    int idx = blockIdx.x * blockDim.x + threadIdx.x;
    if (idx >= Nn * 32) return;
    int n = idx >> 5, c4 = (idx & 31) * 4;
    float4 v = *reinterpret_cast<const float4*>(&g_xcat[(size_t)n * 256 + c4]);
    float4 sc = *reinterpret_cast<const float4*>(&g_bnsc[c4]);
    float4 sh = *reinterpret_cast<const float4*>(&g_bnsh[c4]);
    float4 o;
    o.x = fmaf(v.x, sc.x, sh.x);
    o.y = fmaf(v.y, sc.y, sh.y);
    o.z = fmaf(v.z, sc.z, sh.z);
    o.w = fmaf(v.w, sc.w, sh.w);
    *reinterpret_cast<float4*>(&g_hcat2[(size_t)n * 512 + c4]) = o;
}

__global__ __launch_bounds__(256) void k_poolbn(const float* __restrict__ gammal,
                                                const float* __restrict__ betal) {
    int c = threadIdx.x;
    int g = blockIdx.x;
    float m = g_stats[512 + c] * (1.f / Nn);
    float var = g_stats[768 + c] * (1.f / Nn) - m * m;
    float sc = gammal[c] * rsqrtf(var + EPSb);
    float sh = betal[c] - m * sc;
    float vmax = __int_as_float(g_pmax[g * 256 + c]);
    float vmin = __int_as_float(g_pmin[g * 256 + c]);
    g_pooled[g * 256 + c] = (sc >= 0.f ? sc * vmax : sc * vmin) + sh;
}

// ---------------- head ----------------
__global__ __launch_bounds__(128) void k_head_gemm_relu(const float* __restrict__ A,
                                                        const float* __restrict__ B,
                                                        const float* __restrict__ bias,
                                                        float* __restrict__ Cmat,
                                                        int Kd, int Nc) {
    int idx = blockIdx.x * blockDim.x + threadIdx.x;
    if (idx >= Gg * Nc) return;
    int g = idx / Nc, c = idx - g * Nc;
    float acc = bias[c];
    for (int k = 0; k < Kd; k++) acc = fmaf(A[g * Kd + k], B[k * Nc + c], acc);
    Cmat[idx] = fmaxf(acc, 0.f);
}

__global__ __launch_bounds__(256) void k_head_bn(float* __restrict__ X,
                                                 const float* __restrict__ gamma,
                                                 const float* __restrict__ beta, int Cch) {
    int c = threadIdx.x;
    if (c >= Cch) return;
    float s = 0.f, q = 0.f;
    for (int g = 0; g < Gg; g++) {
        float v = X[g * Cch + c];
        s += v;
        q += v * v;
    }
    float m = s / Gg;
    float var = q / Gg - m * m;
    float sc = gamma[c] * rsqrtf(var + EPSb);
    float sh = beta[c] - m * sc;
    for (int g = 0; g < Gg; g++) X[g * Cch + c] = X[g * Cch + c] * sc + sh;
}

__global__ __launch_bounds__(64) void k_logits(const float* __restrict__ Wf3,
                                               const float* __restrict__ bf3,
                                               float* __restrict__ out) {
    int g = blockIdx.x;
    int c = threadIdx.x;
    __shared__ float sl[64];
    __shared__ float s_m, s_l;
    float v = -INFINITY;
    if (c < Cc) {
        float acc = bf3[c];
        for (int k = 0; k < 128; k++) acc = fmaf(g_f2[g * 128 + k], Wf3[k * Cc + c], acc);
        v = acc;
    }
    sl[c] = v;
    __syncthreads();
    if (c == 0) {
        float m = -INFINITY;
        for (int i = 0; i < Cc; i++) m = fmaxf(m, sl[i]);
        float s = 0.f;
        for (int i = 0; i < Cc; i++) s += expf(sl[i] - m);
        s_m = m;
        s_l = logf(s);
    }
    __syncthreads();
    if (c < Cc) out[g * Cc + c] = sl[c] - s_m - s_l;
}

// ---------------- launch ----------------
extern "C" void kernel_launch(void* const* d_in, const int* in_sizes, int n_in,
                              void* d_out, int out_size) {
    const float* x      = (const float*)d_in[0];
    const int*   ei     = (const int*)d_in[1];
    const float* ea     = (const float*)d_in[2];
    const int*   batch  = (const int*)d_in[3];
    const float* W1     = (const float*)d_in[4];
    const float* b1     = (const float*)d_in[5];
    const float* gamma1 = (const float*)d_in[6];
    const float* beta1  = (const float*)d_in[7];
    const float* W2     = (const float*)d_in[8];
    const float* b2     = (const float*)d_in[9];
    const float* gamma2 = (const float*)d_in[10];
    const float* beta2  = (const float*)d_in[11];
    const float* Wl     = (const float*)d_in[12];
    const float* bl     = (const float*)d_in[13];
    const float* gammal = (const float*)d_in[14];
    const float* betal  = (const float*)d_in[15];
    const float* Wf1    = (const float*)d_in[16];
    const float* bf1    = (const float*)d_in[17];
    const float* gammaf1= (const float*)d_in[18];
    const float* betaf1 = (const float*)d_in[19];
    const float* Wf2    = (const float*)d_in[20];
    const float* bf2    = (const float*)d_in[21];
    const float* gammaf2= (const float*)d_in[22];
    const float* betaf2 = (const float*)d_in[23];
    const float* Wf3    = (const float*)d_in[24];
    const float* bf3    = (const float*)d_in[25];
    const int* row = ei;
    const int* col = ei + Ee;
    float* out = (float*)d_out;

    float *p_hcat1, *p_hcat2, *p_xcat, *p_stats, *p_pooled, *p_f1, *p_f2, *p_deg, *p_bnsc, *p_bnsh;
    int *p_cnt, *p_cur, *p_pmax, *p_pmin;
    unsigned short *p_W2bh, *p_W2bl, *p_Wlbh, *p_Wlbl, *p_W1bh, *p_W1bl;
    cudaGetSymbolAddress((void**)&p_hcat1, g_hcat1);
    cudaGetSymbolAddress((void**)&p_hcat2, g_hcat2);
    cudaGetSymbolAddress((void**)&p_xcat, g_xcat);
    cudaGetSymbolAddress((void**)&p_stats, g_stats);
    cudaGetSymbolAddress((void**)&p_pooled, g_pooled);
    cudaGetSymbolAddress((void**)&p_f1, g_f1);
    cudaGetSymbolAddress((void**)&p_f2, g_f2);
    cudaGetSymbolAddress((void**)&p_deg, g_deg);
    cudaGetSymbolAddress((void**)&p_bnsc, g_bnsc);
    cudaGetSymbolAddress((void**)&p_bnsh, g_bnsh);
    cudaGetSymbolAddress((void**)&p_cnt, g_cnt);
    cudaGetSymbolAddress((void**)&p_cur, g_cur);
    cudaGetSymbolAddress((void**)&p_pmax, g_pmax);
    cudaGetSymbolAddress((void**)&p_pmin, g_pmin);
    cudaGetSymbolAddress((void**)&p_W2bh, g_W2bh);
    cudaGetSymbolAddress((void**)&p_W2bl, g_W2bl);
    cudaGetSymbolAddress((void**)&p_Wlbh, g_Wlbh);
    cudaGetSymbolAddress((void**)&p_Wlbl, g_Wlbl);
    cudaGetSymbolAddress((void**)&p_W1bh, g_W1bh);
    cudaGetSymbolAddress((void**)&p_W1bl, g_W1bl);

    cudaFuncSetAttribute(k_gemm_conv2_mma, cudaFuncAttributeMaxDynamicSharedMemorySize,
                         MMA_SMEM);
    cudaFuncSetAttribute(k_gemm_conv1_mma, cudaFuncAttributeMaxDynamicSharedMemorySize,
                         CMA_SMEM);
    cudaFuncSetAttribute(k_gemm_lin_mma, cudaFuncAttributeMaxDynamicSharedMemorySize,
                         LMA_SMEM);

    cudaMemsetAsync(p_deg, 0, Nn * sizeof(float));
    cudaMemsetAsync(p_cnt, 0, Nn * sizeof(int));
    cudaMemsetAsync(p_cur, 0, Nn * sizeof(int));
    cudaMemsetAsync(p_stats, 0, 1024 * sizeof(float));
    cudaMemsetAsync(p_pmax, 0, Gg * 256 * sizeof(int));
    cudaMemsetAsync(p_pmin, 0x7F, Gg * 256 * sizeof(int));

    k_deg_hist<<<(Ee + 255) / 256, 256>>>(col, ea);
    k_scan<<<1, 256>>>();
    k_scatter<<<(Ee + 255) / 256, 256>>>(row, col, ea);
    k_prepWbf<<<(512 * 128 + 255) / 256, 256>>>(W2, p_W2bh, p_W2bl, 512 * 128);
    k_prepWbf<<<(256 * 256 + 255) / 256, 256>>>(Wl, p_Wlbh, p_Wlbl, 256 * 256);
    k_prepWbf<<<(64 * 128 + 255) / 256, 256>>>(W1, p_W1bh, p_W1bl, 64 * 128);

    // conv1 (mma bf16-split GEMM with fused staged stats)
    k_copyx<<<(Nn * 16 + 255) / 256, 256>>>(x);
    k_prop<4><<<(Nn * 4 + 255) / 256, 256>>>(p_hcat1, 64, 0, 16);
    k_prop<4><<<(Nn * 4 + 255) / 256, 256>>>(p_hcat1, 64, 16, 32);
    k_prop<4><<<(Nn * 4 + 255) / 256, 256>>>(p_hcat1, 64, 32, 48);
    k_gemm_conv1_mma<<<(Nn + 127) / 128, 256, CMA_SMEM>>>(p_hcat1, b1, p_xcat,
                                                          p_stats, p_stats + 128);
    k_bnparam<<<1, 128>>>(p_stats, p_stats + 128, gamma1, beta1, p_bnsc, p_bnsh);
    k_h0<<<(Nn * 32 + 255) / 256, 256>>>();

    // conv2 (mma bf16-split with fused staged stats)
    k_prop<32><<<(Nn * 32 + 255) / 256, 256>>>(p_hcat2, 512, 0, 128);
    k_prop<32><<<(Nn * 32 + 255) / 256, 256>>>(p_hcat2, 512, 128, 256);
    k_prop<32><<<(Nn * 32 + 255) / 256, 256>>>(p_hcat2, 512, 256, 384);
    k_gemm_conv2_mma<<<(Nn + 127) / 128, 256, MMA_SMEM>>>(p_hcat2, b2, p_xcat + 128,
                                                          p_stats + 256, p_stats + 384);
    k_bnparam<<<1, 128>>>(p_stats + 256, p_stats + 384, gamma2, beta2, p_bnsc + 128, p_bnsh + 128);

    // lin1 (mma bf16-split, BN-at-load + fused stats+pool)
    dim3 glin((Nn + 127) / 128, 2);
    k_gemm_lin_mma<<<glin, 256, LMA_SMEM>>>(p_xcat, bl, batch, p_stats + 512, p_stats + 768);
    k_poolbn<<<Gg, 256>>>(gammal, betal);

    // head
    k_head_gemm_relu<<<(Gg * 256 + 127) / 128, 128>>>(p_pooled, Wf1, bf1, p_f1, 256, 256);
    k_head_bn<<<1, 256>>>(p_f1, gammaf1, betaf1, 256);
    k_head_gemm_relu<<<(Gg * 128 + 127) / 128, 128>>>(p_f1, Wf2, bf2, p_f2, 256, 128);
    k_head_bn<<<1, 128>>>(p_f2, gammaf2, betaf2, 128);
    k_logits<<<Gg, 64>>>(Wf3, bf3, out);
}

// round 16
// speedup vs baseline: 1.0649x; 1.0364x over previous
#include <cuda_runtime.h>
#include <cuda_bf16.h>
#include <math.h>

#define Nn 100000
#define Ee 1600000
#define Gg 64
#define Cc 40
#define EPSb 1e-5f

// ---------------- scratch ----------------
__device__ __align__(128) float g_deg[Nn];
__device__ __align__(128) int   g_cnt[Nn];
__device__ __align__(128) int   g_off[Nn];
__device__ __align__(128) int   g_cur[Nn];
__device__ __align__(128) int   g_rowS[Ee];
__device__ __align__(128) float g_wS[Ee];
__device__ __align__(128) float g_hcat1[Nn * 64];
__device__ __align__(128) float g_hcat2[(size_t)Nn * 512];
__device__ __align__(128) float g_xcat[(size_t)Nn * 256];
__device__ __align__(128) float g_stats[1024];
__device__ __align__(128) float g_stats2[768];   // sF1(256) qF1(256) sF2(128) qF2(128)
__device__ __align__(128) float g_bnsc[256];
__device__ __align__(128) float g_bnsh[256];
__device__ __align__(128) int   g_pmax[Gg * 256];
__device__ __align__(128) int   g_pmin[Gg * 256];
__device__ __align__(128) float g_f1[Gg * 256];
__device__ __align__(128) float g_f2[Gg * 128];
__device__ __align__(128) unsigned short g_W2bh[512 * 128];
__device__ __align__(128) unsigned short g_W2bl[512 * 128];
__device__ __align__(128) unsigned short g_Wlbh[256 * 256];
__device__ __align__(128) unsigned short g_Wlbl[256 * 256];
__device__ __align__(128) unsigned short g_W1bh[64 * 128];
__device__ __align__(128) unsigned short g_W1bl[64 * 128];

// ---------------- helpers ----------------
__device__ __forceinline__ unsigned int smem_u32(const void* p) {
    unsigned int a;
    asm("{ .reg .u64 t; cvta.to.shared.u64 t, %1; cvt.u32.u64 %0, t; }" : "=r"(a) : "l"(p));
    return a;
}
__device__ __forceinline__ void cvt_hilo(float a, unsigned short& h, unsigned short& l) {
    __nv_bfloat16 bh = __float2bfloat16(a);
    float r = a - __bfloat162float(bh);
    __nv_bfloat16 bl = __float2bfloat16(r);
    h = __bfloat16_as_ushort(bh);
    l = __bfloat16_as_ushort(bl);
}
__device__ __forceinline__ void ldm_x4(unsigned int* r, unsigned int addr) {
    asm volatile("ldmatrix.sync.aligned.m8n8.x4.shared.b16 {%0,%1,%2,%3}, [%4];"
                 : "=r"(r[0]), "=r"(r[1]), "=r"(r[2]), "=r"(r[3]) : "r"(addr));
}
__device__ __forceinline__ void ldm_x4t(unsigned int* r, unsigned int addr) {
    asm volatile("ldmatrix.sync.aligned.m8n8.x4.trans.shared.b16 {%0,%1,%2,%3}, [%4];"
                 : "=r"(r[0]), "=r"(r[1]), "=r"(r[2]), "=r"(r[3]) : "r"(addr));
}
__device__ __forceinline__ void mma_bf16(float* c, const unsigned int* a, const unsigned int* b) {
    asm volatile(
        "mma.sync.aligned.m16n8k16.row.col.f32.bf16.bf16.f32 "
        "{%0,%1,%2,%3}, {%4,%5,%6,%7}, {%8,%9}, {%0,%1,%2,%3};"
        : "+f"(c[0]), "+f"(c[1]), "+f"(c[2]), "+f"(c[3])
        : "r"(a[0]), "r"(a[1]), "r"(a[2]), "r"(a[3]), "r"(b[0]), "r"(b[1]));
}

// ---------------- unified init ----------------
__global__ __launch_bounds__(256) void k_init() {
    int i = blockIdx.x * blockDim.x + threadIdx.x;
    if (i < Nn) { g_deg[i] = 0.f; g_cnt[i] = 0; g_cur[i] = 0; }
    if (i < 1024) g_stats[i] = 0.f;
    if (i < 768) g_stats2[i] = 0.f;
    if (i < Gg * 256) { g_pmax[i] = 0; g_pmin[i] = 0x7F800000; }
}

// ---------------- graph preprocessing ----------------
__global__ __launch_bounds__(256) void k_deg_hist(const int* __restrict__ col,
                                                  const float* __restrict__ ea) {
    int e = blockIdx.x * blockDim.x + threadIdx.x;
    if (e >= Ee) return;
    int c = col[e];
    atomicAdd(&g_deg[c], ea[e]);
    atomicAdd(&g_cnt[c], 1);
}

__global__ __launch_bounds__(256) void k_scan() {
    __shared__ int ss[256];
    const int CH = (Nn + 255) / 256;
    int t = threadIdx.x;
    int base = t * CH;
    int s = 0;
    for (int i = 0; i < CH; i++) { int idx = base + i; if (idx < Nn) s += g_cnt[idx]; }
    ss[t] = s;
    __syncthreads();
    int own = s;
    for (int o = 1; o < 256; o <<= 1) {
        int v = (t >= o) ? ss[t - o] : 0;
        __syncthreads();
        ss[t] += v;
        __syncthreads();
    }
    int run = ss[t] - own;
    for (int i = 0; i < CH; i++) {
        int idx = base + i;
        if (idx < Nn) { g_off[idx] = run; run += g_cnt[idx]; }
    }
}

__global__ __launch_bounds__(256) void k_scatter(const int* __restrict__ row,
                                                 const int* __restrict__ col,
                                                 const float* __restrict__ ea) {
    int e = blockIdx.x * blockDim.x + threadIdx.x;
    if (e >= Ee) return;
    int r = row[e], c = col[e];
    float dr = g_deg[r], dc = g_deg[c];
    float ir = dr > 0.f ? rsqrtf(dr) : 0.f;
    float ic = dc > 0.f ? rsqrtf(dc) : 0.f;
    float w = ir * ea[e] * ic;
    int p = g_off[c] + atomicAdd(&g_cur[c], 1);
    g_rowS[p] = r;
    g_wS[p] = w;
}

__global__ __launch_bounds__(256) void k_copyx(const float* __restrict__ x) {
    int i = blockIdx.x * blockDim.x + threadIdx.x;
    if (i >= Nn * 16) return;
    int n = i >> 4, j = i & 15;
    g_hcat1[n * 64 + j] = x[i];
}

// CSR gather propagation
template <int TPN>
__global__ __launch_bounds__(256) void k_prop(float* __restrict__ hbase, int stride,
                                              int so, int dofs) {
    int gid = blockIdx.x * blockDim.x + threadIdx.x;
    int node = gid / TPN;
    int part = gid % TPN;
    if (node >= Nn) return;
    int s = g_off[node];
    int e = s + g_cnt[node];
    float4 acc = make_float4(0.f, 0.f, 0.f, 0.f);
    int so4 = so + part * 4;
    for (int i = s; i < e; i++) {
        int r = __ldg(&g_rowS[i]);
        float w = __ldg(&g_wS[i]);
        const float4 v = *reinterpret_cast<const float4*>(hbase + (size_t)r * stride + so4);
        acc.x = fmaf(w, v.x, acc.x);
        acc.y = fmaf(w, v.y, acc.y);
        acc.z = fmaf(w, v.z, acc.z);
        acc.w = fmaf(w, v.w, acc.w);
    }
    *reinterpret_cast<float4*>(hbase + (size_t)node * stride + dofs + part * 4) = acc;
}

// ---------------- weights -> bf16 hi/lo images ----------------
__global__ __launch_bounds__(256) void k_prepWbf(const float* __restrict__ W,
                                                 unsigned short* __restrict__ oh,
                                                 unsigned short* __restrict__ ol, int n) {
    int idx = blockIdx.x * blockDim.x + threadIdx.x;
    if (idx >= n) return;
    unsigned short h, l;
    cvt_hilo(W[idx], h, l);
    oh[idx] = h;
    ol[idx] = l;
}

// =====================================================================
// shared smem layout constants for mma kernels
// =====================================================================
#define MMA_A_HI 0
#define MMA_A_LO 18432
#define MMA_B_HI 36864
#define MMA_B_LO 54272
#define MMA_SMEM 71680
#define STG_RED  67584

// =====================================================================
// conv2 GEMM via mma.sync bf16 split + staged-stats epilogue (R15 winner)
// =====================================================================
__global__ __launch_bounds__(256) void k_gemm_conv2_mma(const float* __restrict__ A,
                                                        const float* __restrict__ bias,
                                                        float* __restrict__ C,
                                                        float* __restrict__ sS,
                                                        float* __restrict__ sQ) {
    extern __shared__ char smem[];
    unsigned int sb = smem_u32(smem);
    int tid = threadIdx.x;
    int lane = tid & 31;
    int wid = tid >> 5;
    int warp_m = wid & 3;
    int warp_n = wid >> 2;
    int row0 = blockIdx.x * 128;

    float acc[2][8][4];
#pragma unroll
    for (int mt = 0; mt < 2; mt++)
#pragma unroll
        for (int nt = 0; nt < 8; nt++)
#pragma unroll
            for (int j = 0; j < 4; j++) acc[mt][nt][j] = 0.f;

    int col4 = tid & 15;
    int rbase = tid >> 4;

    for (int c = 0; c < 8; c++) {
        int kbase = c * 64;
#pragma unroll
        for (int i = 0; i < 8; i++) {
            int r = rbase + i * 16;
            int grow = row0 + r;
            float4 v = make_float4(0.f, 0.f, 0.f, 0.f);
            if (grow < Nn)
                v = *reinterpret_cast<const float4*>(&A[(size_t)grow * 512 + kbase + col4 * 4]);
            unsigned short h0, l0, h1, l1, h2, l2, h3, l3;
            cvt_hilo(v.x, h0, l0);
            cvt_hilo(v.y, h1, l1);
            cvt_hilo(v.z, h2, l2);
            cvt_hilo(v.w, h3, l3);
            int ob = r * 144 + col4 * 8;
            *reinterpret_cast<uint2*>(smem + MMA_A_HI + ob) =
                make_uint2((unsigned)h0 | ((unsigned)h1 << 16), (unsigned)h2 | ((unsigned)h3 << 16));
            *reinterpret_cast<uint2*>(smem + MMA_A_LO + ob) =
                make_uint2((unsigned)l0 | ((unsigned)l1 << 16), (unsigned)l2 | ((unsigned)l3 << 16));
        }
#pragma unroll
        for (int j = 0; j < 4; j++) {
            int idx = tid + j * 256;
            int kr = idx >> 4, c8 = idx & 15;
            int ob = kr * 272 + c8 * 16;
            *reinterpret_cast<uint4*>(smem + MMA_B_HI + ob) =
                *reinterpret_cast<const uint4*>(&g_W2bh[(kbase + kr) * 128 + c8 * 8]);
            *reinterpret_cast<uint4*>(smem + MMA_B_LO + ob) =
                *reinterpret_cast<const uint4*>(&g_W2bl[(kbase + kr) * 128 + c8 * 8]);
        }
        __syncthreads();

#pragma unroll
        for (int ks = 0; ks < 4; ks++) {
            unsigned int Ah[2][4], Al[2][4], Bf[4][4];
            int arow = (lane & 15);
            int acolb = ks * 32 + (lane >> 4) * 16;
#pragma unroll
            for (int mt = 0; mt < 2; mt++) {
                int m0 = warp_m * 32 + mt * 16;
                unsigned int aoff = (unsigned)((m0 + arow) * 144 + acolb);
                ldm_x4(Ah[mt], sb + MMA_A_HI + aoff);
                ldm_x4(Al[mt], sb + MMA_A_LO + aoff);
            }
            int brow = ks * 16 + (lane & 15);
#pragma unroll
            for (int p = 0; p < 4; p++) {
                unsigned int boff = (unsigned)(brow * 272 + (warp_n * 64 + p * 16 + (lane >> 4) * 8) * 2);
                ldm_x4t(Bf[p], sb + MMA_B_HI + boff);
            }
#pragma unroll
            for (int mt = 0; mt < 2; mt++)
#pragma unroll
                for (int p = 0; p < 4; p++) {
                    mma_bf16(acc[mt][2 * p],     Ah[mt], &Bf[p][0]);
                    mma_bf16(acc[mt][2 * p + 1], Ah[mt], &Bf[p][2]);
                    mma_bf16(acc[mt][2 * p],     Al[mt], &Bf[p][0]);
                    mma_bf16(acc[mt][2 * p + 1], Al[mt], &Bf[p][2]);
                }
#pragma unroll
            for (int p = 0; p < 4; p++) {
                unsigned int boff = (unsigned)(brow * 272 + (warp_n * 64 + p * 16 + (lane >> 4) * 8) * 2);
                ldm_x4t(Bf[p], sb + MMA_B_LO + boff);
            }
#pragma unroll
            for (int mt = 0; mt < 2; mt++)
#pragma unroll
                for (int p = 0; p < 4; p++) {
                    mma_bf16(acc[mt][2 * p],     Ah[mt], &Bf[p][0]);
                    mma_bf16(acc[mt][2 * p + 1], Ah[mt], &Bf[p][2]);
                }
        }
        __syncthreads();
    }

    float* stg = reinterpret_cast<float*>(smem);
    float* red = reinterpret_cast<float*>(smem + STG_RED);
    red[tid] = 0.f;
#pragma unroll
    for (int mt = 0; mt < 2; mt++) {
        int rloc = warp_m * 32 + mt * 16 + (lane >> 2);
        int r0 = row0 + rloc;
#pragma unroll
        for (int nt = 0; nt < 8; nt++) {
            int cloc = warp_n * 64 + nt * 8 + (lane & 3) * 2;
            float b0 = __ldg(&bias[cloc]), b1 = __ldg(&bias[cloc + 1]);
            float o0 = fmaxf(acc[mt][nt][0] + b0, 0.f);
            float o1 = fmaxf(acc[mt][nt][1] + b1, 0.f);
            float o2 = fmaxf(acc[mt][nt][2] + b0, 0.f);
            float o3 = fmaxf(acc[mt][nt][3] + b1, 0.f);
            stg[rloc * 132 + cloc]           = o0;
            stg[rloc * 132 + cloc + 1]       = o1;
            stg[(rloc + 8) * 132 + cloc]     = o2;
            stg[(rloc + 8) * 132 + cloc + 1] = o3;
            if (r0 < Nn)
                *reinterpret_cast<float2*>(&C[(size_t)r0 * 256 + cloc]) = make_float2(o0, o1);
            if (r0 + 8 < Nn)
                *reinterpret_cast<float2*>(&C[(size_t)(r0 + 8) * 256 + cloc]) = make_float2(o2, o3);
        }
    }
    __syncthreads();

    int ty = tid >> 4, tx = tid & 15;
    float s[8], q[8];
#pragma unroll
    for (int j = 0; j < 8; j++) { s[j] = 0.f; q[j] = 0.f; }
#pragma unroll
    for (int i = 0; i < 8; i++) {
        int row = row0 + ty * 8 + i;
        if (row >= Nn) continue;
#pragma unroll
        for (int j = 0; j < 8; j++) {
            float v = stg[(ty * 8 + i) * 132 + tx * 8 + j];
            s[j] += v;
            q[j] = fmaf(v, v, q[j]);
        }
    }
#pragma unroll
    for (int j = 0; j < 8; j++) {
        atomicAdd(&red[tx * 8 + j], s[j]);
        atomicAdd(&red[128 + tx * 8 + j], q[j]);
    }
    __syncthreads();
    if (tid < 128) atomicAdd(&sS[tid], red[tid]);
    else           atomicAdd(&sQ[tid - 128], red[tid]);
}

// =====================================================================
// conv1 GEMM via mma.sync bf16 split (R13 winner, unchanged)
// =====================================================================
#define CMA_RED 67584
#define CMA_SMEM 71680

__global__ __launch_bounds__(256) void k_gemm_conv1_mma(const float* __restrict__ A,
                                                        const float* __restrict__ bias,
                                                        float* __restrict__ C,
                                                        float* __restrict__ sS,
                                                        float* __restrict__ sQ) {
    extern __shared__ char smem[];
    unsigned int sb = smem_u32(smem);
    int tid = threadIdx.x;
    int lane = tid & 31;
    int wid = tid >> 5;
    int warp_m = wid & 3;
    int warp_n = wid >> 2;
    int row0 = blockIdx.x * 128;

    float acc[2][8][4];
#pragma unroll
    for (int mt = 0; mt < 2; mt++)
#pragma unroll
        for (int nt = 0; nt < 8; nt++)
#pragma unroll
            for (int j = 0; j < 4; j++) acc[mt][nt][j] = 0.f;

    int col4 = tid & 15;
    int rbase = tid >> 4;

#pragma unroll
    for (int i = 0; i < 8; i++) {
        int r = rbase + i * 16;
        int grow = row0 + r;
        float4 v = make_float4(0.f, 0.f, 0.f, 0.f);
        if (grow < Nn)
            v = *reinterpret_cast<const float4*>(&A[(size_t)grow * 64 + col4 * 4]);
        unsigned short h0, l0, h1, l1, h2, l2, h3, l3;
        cvt_hilo(v.x, h0, l0);
        cvt_hilo(v.y, h1, l1);
        cvt_hilo(v.z, h2, l2);
        cvt_hilo(v.w, h3, l3);
        int ob = r * 144 + col4 * 8;
        *reinterpret_cast<uint2*>(smem + MMA_A_HI + ob) =
            make_uint2((unsigned)h0 | ((unsigned)h1 << 16), (unsigned)h2 | ((unsigned)h3 << 16));
        *reinterpret_cast<uint2*>(smem + MMA_A_LO + ob) =
            make_uint2((unsigned)l0 | ((unsigned)l1 << 16), (unsigned)l2 | ((unsigned)l3 << 16));
    }
#pragma unroll
    for (int j = 0; j < 4; j++) {
        int idx = tid + j * 256;
        int kr = idx >> 4, c8 = idx & 15;
        int ob = kr * 272 + c8 * 16;
        *reinterpret_cast<uint4*>(smem + MMA_B_HI + ob) =
            *reinterpret_cast<const uint4*>(&g_W1bh[kr * 128 + c8 * 8]);
        *reinterpret_cast<uint4*>(smem + MMA_B_LO + ob) =
            *reinterpret_cast<const uint4*>(&g_W1bl[kr * 128 + c8 * 8]);
    }
    __syncthreads();

#pragma unroll
    for (int ks = 0; ks < 4; ks++) {
        unsigned int Ah[2][4], Al[2][4], Bf[4][4];
        int arow = (lane & 15);
        int acolb = ks * 32 + (lane >> 4) * 16;
#pragma unroll
        for (int mt = 0; mt < 2; mt++) {
            int m0 = warp_m * 32 + mt * 16;
            unsigned int aoff = (unsigned)((m0 + arow) * 144 + acolb);
            ldm_x4(Ah[mt], sb + MMA_A_HI + aoff);
            ldm_x4(Al[mt], sb + MMA_A_LO + aoff);
        }
        int brow = ks * 16 + (lane & 15);
#pragma unroll
        for (int p = 0; p < 4; p++) {
            unsigned int boff = (unsigned)(brow * 272 + (warp_n * 64 + p * 16 + (lane >> 4) * 8) * 2);
            ldm_x4t(Bf[p], sb + MMA_B_HI + boff);
        }
#pragma unroll
        for (int mt = 0; mt < 2; mt++)
#pragma unroll
            for (int p = 0; p < 4; p++) {
                mma_bf16(acc[mt][2 * p],     Ah[mt], &Bf[p][0]);
                mma_bf16(acc[mt][2 * p + 1], Ah[mt], &Bf[p][2]);
                mma_bf16(acc[mt][2 * p],     Al[mt], &Bf[p][0]);
                mma_bf16(acc[mt][2 * p + 1], Al[mt], &Bf[p][2]);
            }
#pragma unroll
        for (int p = 0; p < 4; p++) {
            unsigned int boff = (unsigned)(brow * 272 + (warp_n * 64 + p * 16 + (lane >> 4) * 8) * 2);
            ldm_x4t(Bf[p], sb + MMA_B_LO + boff);
        }
#pragma unroll
        for (int mt = 0; mt < 2; mt++)
#pragma unroll
            for (int p = 0; p < 4; p++) {
                mma_bf16(acc[mt][2 * p],     Ah[mt], &Bf[p][0]);
                mma_bf16(acc[mt][2 * p + 1], Ah[mt], &Bf[p][2]);
            }
    }
    __syncthreads();

    float* stg = reinterpret_cast<float*>(smem);
    float* red = reinterpret_cast<float*>(smem + CMA_RED);
    red[tid] = 0.f;
#pragma unroll
    for (int mt = 0; mt < 2; mt++) {
        int rloc = warp_m * 32 + mt * 16 + (lane >> 2);
        int r0 = row0 + rloc;
#pragma unroll
        for (int nt = 0; nt < 8; nt++) {
            int cloc = warp_n * 64 + nt * 8 + (lane & 3) * 2;
            float b0 = __ldg(&bias[cloc]), b1 = __ldg(&bias[cloc + 1]);
            float o0 = fmaxf(acc[mt][nt][0] + b0, 0.f);
            float o1 = fmaxf(acc[mt][nt][1] + b1, 0.f);
            float o2 = fmaxf(acc[mt][nt][2] + b0, 0.f);
            float o3 = fmaxf(acc[mt][nt][3] + b1, 0.f);
            stg[rloc * 132 + cloc]           = o0;
            stg[rloc * 132 + cloc + 1]       = o1;
            stg[(rloc + 8) * 132 + cloc]     = o2;
            stg[(rloc + 8) * 132 + cloc + 1] = o3;
            if (r0 < Nn)
                *reinterpret_cast<float2*>(&C[(size_t)r0 * 256 + cloc]) = make_float2(o0, o1);
            if (r0 + 8 < Nn)
                *reinterpret_cast<float2*>(&C[(size_t)(r0 + 8) * 256 + cloc]) = make_float2(o2, o3);
        }
    }
    __syncthreads();

    int ty = tid >> 4, tx = tid & 15;
    float s[8], q[8];
#pragma unroll
    for (int j = 0; j < 8; j++) { s[j] = 0.f; q[j] = 0.f; }
#pragma unroll
    for (int i = 0; i < 8; i++) {
        int row = row0 + ty * 8 + i;
        if (row >= Nn) continue;
#pragma unroll
        for (int j = 0; j < 8; j++) {
            float v = stg[(ty * 8 + i) * 132 + tx * 8 + j];
            s[j] += v;
            q[j] = fmaf(v, v, q[j]);
        }
    }
#pragma unroll
    for (int j = 0; j < 8; j++) {
        atomicAdd(&red[tx * 8 + j], s[j]);
        atomicAdd(&red[128 + tx * 8 + j], q[j]);
    }
    __syncthreads();
    if (tid < 128) atomicAdd(&sS[tid], red[tid]);
    else           atomicAdd(&sQ[tid - 128], red[tid]);
}

// =====================================================================
// lin1 GEMM via mma.sync bf16 split (R10 winner, unchanged)
// =====================================================================
#define LMA_STAGE 0
#define LMA_RED   67584
#define LMA_PMAX  68608
#define LMA_PMIN  70656
#define LMA_SMEM  72704

__global__ __launch_bounds__(256) void k_gemm_lin_mma(const float* __restrict__ A,
                                                      const float* __restrict__ bias,
                                                      const int* __restrict__ batch,
                                                      float* __restrict__ sS,
                                                      float* __restrict__ sQ) {
    extern __shared__ char smem[];
    __shared__ float sbn_sc[256], sbn_sh[256];
    unsigned int sb = smem_u32(smem);
    int tid = threadIdx.x;
    int lane = tid & 31;
    int wid = tid >> 5;
    int warp_m = wid & 3;
    int warp_n = wid >> 2;
    int row0 = blockIdx.x * 128;
    int col0 = blockIdx.y * 128;
    sbn_sc[tid] = g_bnsc[tid];
    sbn_sh[tid] = g_bnsh[tid];
    __syncthreads();

    float acc[2][8][4];
#pragma unroll
    for (int mt = 0; mt < 2; mt++)
#pragma unroll
        for (int nt = 0; nt < 8; nt++)
#pragma unroll
            for (int j = 0; j < 4; j++) acc[mt][nt][j] = 0.f;

    int col4 = tid & 15;
    int rbase = tid >> 4;

    for (int c = 0; c < 4; c++) {
        int kbase = c * 64;
#pragma unroll
        for (int i = 0; i < 8; i++) {
            int r = rbase + i * 16;
            int grow = row0 + r;
            float4 v = make_float4(0.f, 0.f, 0.f, 0.f);
            if (grow < Nn) {
                v = *reinterpret_cast<const float4*>(&A[(size_t)grow * 256 + kbase + col4 * 4]);
                int kc = kbase + col4 * 4;
                v.x = fmaf(v.x, sbn_sc[kc],     sbn_sh[kc]);
                v.y = fmaf(v.y, sbn_sc[kc + 1], sbn_sh[kc + 1]);
                v.z = fmaf(v.z, sbn_sc[kc + 2], sbn_sh[kc + 2]);
                v.w = fmaf(v.w, sbn_sc[kc + 3], sbn_sh[kc + 3]);
            }
            unsigned short h0, l0, h1, l1, h2, l2, h3, l3;
            cvt_hilo(v.x, h0, l0);
            cvt_hilo(v.y, h1, l1);
            cvt_hilo(v.z, h2, l2);
            cvt_hilo(v.w, h3, l3);
            int ob = r * 144 + col4 * 8;
            *reinterpret_cast<uint2*>(smem + MMA_A_HI + ob) =
                make_uint2((unsigned)h0 | ((unsigned)h1 << 16), (unsigned)h2 | ((unsigned)h3 << 16));
            *reinterpret_cast<uint2*>(smem + MMA_A_LO + ob) =
                make_uint2((unsigned)l0 | ((unsigned)l1 << 16), (unsigned)l2 | ((unsigned)l3 << 16));
        }
#pragma unroll
        for (int j = 0; j < 4; j++) {
            int idx = tid + j * 256;
            int kr = idx >> 4, c8 = idx & 15;
            int ob = kr * 272 + c8 * 16;
            *reinterpret_cast<uint4*>(smem + MMA_B_HI + ob) =
                *reinterpret_cast<const uint4*>(&g_Wlbh[(kbase + kr) * 256 + col0 + c8 * 8]);
            *reinterpret_cast<uint4*>(smem + MMA_B_LO + ob) =
                *reinterpret_cast<const uint4*>(&g_Wlbl[(kbase + kr) * 256 + col0 + c8 * 8]);
        }
        __syncthreads();

#pragma unroll
        for (int ks = 0; ks < 4; ks++) {
            unsigned int Ah[2][4], Al[2][4], Bf[4][4];
            int arow = (lane & 15);
            int acolb = ks * 32 + (lane >> 4) * 16;
#pragma unroll
            for (int mt = 0; mt < 2; mt++) {
                int m0 = warp_m * 32 + mt * 16;
                unsigned int aoff = (unsigned)((m0 + arow) * 144 + acolb);
                ldm_x4(Ah[mt], sb + MMA_A_HI + aoff);
                ldm_x4(Al[mt], sb + MMA_A_LO + aoff);
            }
            int brow = ks * 16 + (lane & 15);
#pragma unroll
            for (int p = 0; p < 4; p++) {
                unsigned int boff = (unsigned)(brow * 272 + (warp_n * 64 + p * 16 + (lane >> 4) * 8) * 2);
                ldm_x4t(Bf[p], sb + MMA_B_HI + boff);
            }
#pragma unroll
            for (int mt = 0; mt < 2; mt++)
#pragma unroll
                for (int p = 0; p < 4; p++) {
                    mma_bf16(acc[mt][2 * p],     Ah[mt], &Bf[p][0]);
                    mma_bf16(acc[mt][2 * p + 1], Ah[mt], &Bf[p][2]);
                    mma_bf16(acc[mt][2 * p],     Al[mt], &Bf[p][0]);
                    mma_bf16(acc[mt][2 * p + 1], Al[mt], &Bf[p][2]);
                }
#pragma unroll
            for (int p = 0; p < 4; p++) {
                unsigned int boff = (unsigned)(brow * 272 + (warp_n * 64 + p * 16 + (lane >> 4) * 8) * 2);
                ldm_x4t(Bf[p], sb + MMA_B_LO + boff);
            }
#pragma unroll
            for (int mt = 0; mt < 2; mt++)
#pragma unroll
                for (int p = 0; p < 4; p++) {
                    mma_bf16(acc[mt][2 * p],     Ah[mt], &Bf[p][0]);
                    mma_bf16(acc[mt][2 * p + 1], Ah[mt], &Bf[p][2]);
                }
        }
        __syncthreads();
    }

    float* stg = reinterpret_cast<float*>(smem + LMA_STAGE);
#pragma unroll
    for (int mt = 0; mt < 2; mt++) {
        int rloc = warp_m * 32 + mt * 16 + (lane >> 2);
#pragma unroll
        for (int nt = 0; nt < 8; nt++) {
            int cloc = warp_n * 64 + nt * 8 + (lane & 3) * 2;
            float b0 = __ldg(&bias[col0 + cloc]), b1 = __ldg(&bias[col0 + cloc + 1]);
            stg[rloc * 132 + cloc]           = fmaxf(acc[mt][nt][0] + b0, 0.f);
            stg[rloc * 132 + cloc + 1]       = fmaxf(acc[mt][nt][1] + b1, 0.f);
            stg[(rloc + 8) * 132 + cloc]     = fmaxf(acc[mt][nt][2] + b0, 0.f);
            stg[(rloc + 8) * 132 + cloc + 1] = fmaxf(acc[mt][nt][3] + b1, 0.f);
        }
    }
    float* red  = reinterpret_cast<float*>(smem + LMA_RED);
    int*  pmaxS = reinterpret_cast<int*>(smem + LMA_PMAX);
    int*  pminS = reinterpret_cast<int*>(smem + LMA_PMIN);
    red[tid] = 0.f;
    pmaxS[tid] = 0; pmaxS[tid + 256] = 0;
    pminS[tid] = 0x7F800000; pminS[tid + 256] = 0x7F800000;
    __syncthreads();

    int ty = tid >> 4, tx = tid & 15;
    int gbase = batch[row0];
    float s[8], q[8], vmx[8], vmn[8];
#pragma unroll
    for (int j = 0; j < 8; j++) { s[j] = 0.f; q[j] = 0.f; vmx[j] = 0.f; vmn[j] = __int_as_float(0x7F800000); }
    int cur_slot = -1;
#pragma unroll
    for (int i = 0; i < 8; i++) {
        int row = row0 + ty * 8 + i;
        if (row >= Nn) continue;
        int slot = batch[row] - gbase;
        if (slot != cur_slot) {
            if (cur_slot >= 0) {
#pragma unroll
                for (int j = 0; j < 8; j++) {
                    int c = tx * 8 + j;
                    if (cur_slot < 4) {
                        atomicMax(&pmaxS[cur_slot * 128 + c], __float_as_int(vmx[j]));
                        atomicMin(&pminS[cur_slot * 128 + c], __float_as_int(vmn[j]));
                    } else {
                        atomicMax(&g_pmax[(gbase + cur_slot) * 256 + col0 + c], __float_as_int(vmx[j]));
                        atomicMin(&g_pmin[(gbase + cur_slot) * 256 + col0 + c], __float_as_int(vmn[j]));
                    }
                    vmx[j] = 0.f; vmn[j] = __int_as_float(0x7F800000);
                }
            }
            cur_slot = slot;
        }
#pragma unroll
        for (int j = 0; j < 8; j++) {
            float v = stg[(ty * 8 + i) * 132 + tx * 8 + j];
            s[j] += v;
            q[j] = fmaf(v, v, q[j]);
            vmx[j] = fmaxf(vmx[j], v);
            vmn[j] = fminf(vmn[j], v);
        }
    }
    if (cur_slot >= 0) {
#pragma unroll
        for (int j = 0; j < 8; j++) {
            int c = tx * 8 + j;
            if (cur_slot < 4) {
                atomicMax(&pmaxS[cur_slot * 128 + c], __float_as_int(vmx[j]));
                atomicMin(&pminS[cur_slot * 128 + c], __float_as_int(vmn[j]));
            } else {
                atomicMax(&g_pmax[(gbase + cur_slot) * 256 + col0 + c], __float_as_int(vmx[j]));
                atomicMin(&g_pmin[(gbase + cur_slot) * 256 + col0 + c], __float_as_int(vmn[j]));
            }
        }
    }
#pragma unroll
    for (int j = 0; j < 8; j++) {
        atomicAdd(&red[tx * 8 + j], s[j]);
        atomicAdd(&red[128 + tx * 8 + j], q[j]);
    }
    __syncthreads();
    if (tid < 128) {
        atomicAdd(&sS[col0 + tid], red[tid]);
#pragma unroll
        for (int sl = 0; sl < 4; sl++) {
            int g = gbase + sl;
            if (g < Gg) {
                atomicMax(&g_pmax[g * 256 + col0 + tid], pmaxS[sl * 128 + tid]);
                atomicMin(&g_pmin[g * 256 + col0 + tid], pminS[sl * 128 + tid]);
            }
        }
    } else {
        atomicAdd(&sQ[col0 + tid - 128], red[tid]);
    }
}

// ---------------- BN params / h0 ----------------
__global__ __launch_bounds__(128) void k_bnparam(const float* __restrict__ sS,
                                                 const float* __restrict__ sQ,
                                                 const float* __restrict__ gamma,
                                                 const float* __restrict__ beta,
                                                 float* __restrict__ osc,
                                                 float* __restrict__ osh) {
    int c = threadIdx.x;
    float m = sS[c] * (1.f / Nn);
    float var = sQ[c] * (1.f / Nn) - m * m;
    float sc = gamma[c] * rsqrtf(var + EPSb);
    osc[c] = sc;
    osh[c] = beta[c] - m * sc;
}

__global__ __launch_bounds__(256) void k_h0() {
    int idx = blockIdx.x * blockDim.x + threadIdx.x;
    if (idx >= Nn * 32) return;
    int n = idx >> 5, c4 = (idx & 31) * 4;
    float4 v = *reinterpret_cast<const float4*>(&g_xcat[(size_t)n * 256 + c4]);
    float4 sc = *reinterpret_cast<const float4*>(&g_bnsc[c4]);
    float4 sh = *reinterpret_cast<const float4*>(&g_bnsh[c4]);
    float4 o;
    o.x = fmaf(v.x, sc.x, sh.x);
    o.y = fmaf(v.y, sc.y, sh.y);
    o.z = fmaf(v.z, sc.z, sh.z);
    o.w = fmaf(v.w, sc.w, sh.w);
    *reinterpret_cast<float4*>(&g_hcat2[(size_t)n * 512 + c4]) = o;
}

// ---------------- merged head: 3 kernels ----------------
// head1: pooled BN inline -> f1 = relu(pooled@Wf1+bf1) -> stats2[0:512]
__global__ __launch_bounds__(256) void k_head1(const float* __restrict__ gammal,
                                               const float* __restrict__ betal,
                                               const float* __restrict__ Wf1,
                                               const float* __restrict__ bf1) {
    __shared__ float ps[256];
    int g = blockIdx.x, c = threadIdx.x;
    float m = g_stats[512 + c] * (1.f / Nn);
    float var = g_stats[768 + c] * (1.f / Nn) - m * m;
    float sc = gammal[c] * rsqrtf(var + EPSb);
    float sh = betal[c] - m * sc;
    float vmax = __int_as_float(g_pmax[g * 256 + c]);
    float vmin = __int_as_float(g_pmin[g * 256 + c]);
    ps[c] = (sc >= 0.f ? sc * vmax : sc * vmin) + sh;
    __syncthreads();
    float acc = bf1[c];
    for (int k = 0; k < 256; k++) acc = fmaf(ps[k], Wf1[k * 256 + c], acc);
    float o = fmaxf(acc, 0.f);
    g_f1[g * 256 + c] = o;
    atomicAdd(&g_stats2[c], o);
    atomicAdd(&g_stats2[256 + c], o * o);
}

// head2: BNf1-at-load -> f2 = relu(f1n@Wf2+bf2) -> stats2[512:768]
__global__ __launch_bounds__(128) void k_head2(const float* __restrict__ gammaf1,
                                               const float* __restrict__ betaf1,
                                               const float* __restrict__ Wf2,
                                               const float* __restrict__ bf2) {
    __shared__ float fs[256];
    int g = blockIdx.x, t = threadIdx.x;
    for (int j = t; j < 256; j += 128) {
        float m = g_stats2[j] * (1.f / Gg);
        float var = g_stats2[256 + j] * (1.f / Gg) - m * m;
        float sc = gammaf1[j] * rsqrtf(var + EPSb);
        float sh = betaf1[j] - m * sc;
        fs[j] = fmaf(g_f1[g * 256 + j], sc, sh);
    }
    __syncthreads();
    float acc = bf2[t];
    for (int k = 0; k < 256; k++) acc = fmaf(fs[k], Wf2[k * 128 + t], acc);
    float o = fmaxf(acc, 0.f);
    g_f2[g * 128 + t] = o;
    atomicAdd(&g_stats2[512 + t], o);
    atomicAdd(&g_stats2[640 + t], o * o);
}

// logits: BNf2-at-load -> logits -> log_softmax
__global__ __launch_bounds__(128) void k_logits(const float* __restrict__ gammaf2,
                                                const float* __restrict__ betaf2,
                                                const float* __restrict__ Wf3,
                                                const float* __restrict__ bf3,
                                                float* __restrict__ out) {
    __shared__ float fs[128], sl[64];
    __shared__ float s_m, s_l;
    int g = blockIdx.x, t = threadIdx.x;
    {
        float m = g_stats2[512 + t] * (1.f / Gg);
        float var = g_stats2[640 + t] * (1.f / Gg) - m * m;
        float sc = gammaf2[t] * rsqrtf(var + EPSb);
        float sh = betaf2[t] - m * sc;
        fs[t] = fmaf(g_f2[g * 128 + t], sc, sh);
    }
    __syncthreads();
    if (t < Cc) {
        float acc = bf3[t];
        for (int k = 0; k < 128; k++) acc = fmaf(fs[k], Wf3[k * Cc + t], acc);
        sl[t] = acc;
    }
    __syncthreads();
    if (t == 0) {
        float m = -INFINITY;
        for (int i = 0; i < Cc; i++) m = fmaxf(m, sl[i]);
        float s = 0.f;
        for (int i = 0; i < Cc; i++) s += expf(sl[i] - m);
        s_m = m;
        s_l = logf(s);
    }
    __syncthreads();
    if (t < Cc) out[g * Cc + t] = sl[t] - s_m - s_l;
}

// ---------------- launch ----------------
extern "C" void kernel_launch(void* const* d_in, const int* in_sizes, int n_in,
                              void* d_out, int out_size) {
    const float* x      = (const float*)d_in[0];
    const int*   ei     = (const int*)d_in[1];
    const float* ea     = (const float*)d_in[2];
    const int*   batch  = (const int*)d_in[3];
    const float* W1     = (const float*)d_in[4];
    const float* b1     = (const float*)d_in[5];
    const float* gamma1 = (const float*)d_in[6];
    const float* beta1  = (const float*)d_in[7];
    const float* W2     = (const float*)d_in[8];
    const float* b2     = (const float*)d_in[9];
    const float* gamma2 = (const float*)d_in[10];
    const float* beta2  = (const float*)d_in[11];
    const float* Wl     = (const float*)d_in[12];
    const float* bl     = (const float*)d_in[13];
    const float* gammal = (const float*)d_in[14];
    const float* betal  = (const float*)d_in[15];
    const float* Wf1    = (const float*)d_in[16];
    const float* bf1    = (const float*)d_in[17];
    const float* gammaf1= (const float*)d_in[18];
    const float* betaf1 = (const float*)d_in[19];
    const float* Wf2    = (const float*)d_in[20];
    const float* bf2    = (const float*)d_in[21];
    const float* gammaf2= (const float*)d_in[22];
    const float* betaf2 = (const float*)d_in[23];
    const float* Wf3    = (const float*)d_in[24];
    const float* bf3    = (const float*)d_in[25];
    const int* row = ei;
    const int* col = ei + Ee;
    float* out = (float*)d_out;

    float *p_hcat1, *p_hcat2, *p_xcat, *p_stats, *p_bnsc, *p_bnsh;
    unsigned short *p_W2bh, *p_W2bl, *p_Wlbh, *p_Wlbl, *p_W1bh, *p_W1bl;
    cudaGetSymbolAddress((void**)&p_hcat1, g_hcat1);
    cudaGetSymbolAddress((void**)&p_hcat2, g_hcat2);
    cudaGetSymbolAddress((void**)&p_xcat, g_xcat);
    cudaGetSymbolAddress((void**)&p_stats, g_stats);
    cudaGetSymbolAddress((void**)&p_bnsc, g_bnsc);
    cudaGetSymbolAddress((void**)&p_bnsh, g_bnsh);
    cudaGetSymbolAddress((void**)&p_W2bh, g_W2bh);
    cudaGetSymbolAddress((void**)&p_W2bl, g_W2bl);
    cudaGetSymbolAddress((void**)&p_Wlbh, g_Wlbh);
    cudaGetSymbolAddress((void**)&p_Wlbl, g_Wlbl);
    cudaGetSymbolAddress((void**)&p_W1bh, g_W1bh);
    cudaGetSymbolAddress((void**)&p_W1bl, g_W1bl);

    cudaFuncSetAttribute(k_gemm_conv2_mma, cudaFuncAttributeMaxDynamicSharedMemorySize,
                         MMA_SMEM);
    cudaFuncSetAttribute(k_gemm_conv1_mma, cudaFuncAttributeMaxDynamicSharedMemorySize,
                         CMA_SMEM);
    cudaFuncSetAttribute(k_gemm_lin_mma, cudaFuncAttributeMaxDynamicSharedMemorySize,
                         LMA_SMEM);

    // unified scratch init (replaces 6 memsets)
    k_init<<<(Nn + 255) / 256, 256>>>();

    k_deg_hist<<<(Ee + 255) / 256, 256>>>(col, ea);
    k_scan<<<1, 256>>>();
    k_scatter<<<(Ee + 255) / 256, 256>>>(row, col, ea);
    k_prepWbf<<<(512 * 128 + 255) / 256, 256>>>(W2, p_W2bh, p_W2bl, 512 * 128);
    k_prepWbf<<<(256 * 256 + 255) / 256, 256>>>(Wl, p_Wlbh, p_Wlbl, 256 * 256);
    k_prepWbf<<<(64 * 128 + 255) / 256, 256>>>(W1, p_W1bh, p_W1bl, 64 * 128);

    // conv1 (mma bf16-split GEMM with fused staged stats)
    k_copyx<<<(Nn * 16 + 255) / 256, 256>>>(x);
    k_prop<4><<<(Nn * 4 + 255) / 256, 256>>>(p_hcat1, 64, 0, 16);
    k_prop<4><<<(Nn * 4 + 255) / 256, 256>>>(p_hcat1, 64, 16, 32);
    k_prop<4><<<(Nn * 4 + 255) / 256, 256>>>(p_hcat1, 64, 32, 48);
    k_gemm_conv1_mma<<<(Nn + 127) / 128, 256, CMA_SMEM>>>(p_hcat1, b1, p_xcat,
                                                          p_stats, p_stats + 128);
    k_bnparam<<<1, 128>>>(p_stats, p_stats + 128, gamma1, beta1, p_bnsc, p_bnsh);
    k_h0<<<(Nn * 32 + 255) / 256, 256>>>();

    // conv2 (mma bf16-split with fused staged stats)
    k_prop<32><<<(Nn * 32 + 255) / 256, 256>>>(p_hcat2, 512, 0, 128);
    k_prop<32><<<(Nn * 32 + 255) / 256, 256>>>(p_hcat2, 512, 128, 256);
    k_prop<32><<<(Nn * 32 + 255) / 256, 256>>>(p_hcat2, 512, 256, 384);
    k_gemm_conv2_mma<<<(Nn + 127) / 128, 256, MMA_SMEM>>>(p_hcat2, b2, p_xcat + 128,
                                                          p_stats + 256, p_stats + 384);
    k_bnparam<<<1, 128>>>(p_stats + 256, p_stats + 384, gamma2, beta2, p_bnsc + 128, p_bnsh + 128);

    // lin1 (mma bf16-split, BN-at-load + fused stats+pool)
    dim3 glin((Nn + 127) / 128, 2);
    k_gemm_lin_mma<<<glin, 256, LMA_SMEM>>>(p_xcat, bl, batch, p_stats + 512, p_stats + 768);

    // merged head: poolbn+gemm1, bn+gemm2, bn+logits
    k_head1<<<Gg, 256>>>(gammal, betal, Wf1, bf1);
    k_head2<<<Gg, 128>>>(gammaf1, betaf1, Wf2, bf2);
    k_logits<<<Gg, 128>>>(gammaf2, betaf2, Wf3, bf3, out);
}

// round 17
// speedup vs baseline: 1.0732x; 1.0078x over previous
#include <cuda_runtime.h>
#include <cuda_bf16.h>
#include <math.h>

#define Nn 100000
#define Ee 1600000
#define Gg 64
#define Cc 40
#define EPSb 1e-5f

// ---------------- scratch ----------------
__device__ __align__(128) float g_deg[Nn];
__device__ __align__(128) int   g_cnt[Nn];
__device__ __align__(128) int   g_off[Nn];
__device__ __align__(128) int   g_cur[Nn];
__device__ __align__(128) int   g_rowS[Ee];
__device__ __align__(128) float g_wS[Ee];
__device__ __align__(128) float g_hcat1[Nn * 64];
__device__ __align__(128) float g_hcat2[(size_t)Nn * 512];
__device__ __align__(128) float g_xcat[(size_t)Nn * 256];
__device__ __align__(128) float g_stats[1024];
__device__ __align__(128) float g_stats2[768];
__device__ __align__(128) int   g_pmax[Gg * 256];
__device__ __align__(128) int   g_pmin[Gg * 256];
__device__ __align__(128) float g_f1[Gg * 256];
__device__ __align__(128) float g_f2[Gg * 128];
__device__ __align__(128) unsigned short g_W2bh[512 * 128];
__device__ __align__(128) unsigned short g_W2bl[512 * 128];
__device__ __align__(128) unsigned short g_Wlbh[256 * 256];
__device__ __align__(128) unsigned short g_Wlbl[256 * 256];
__device__ __align__(128) unsigned short g_W1bh[64 * 128];
__device__ __align__(128) unsigned short g_W1bl[64 * 128];

// ---------------- helpers ----------------
__device__ __forceinline__ unsigned int smem_u32(const void* p) {
    unsigned int a;
    asm("{ .reg .u64 t; cvta.to.shared.u64 t, %1; cvt.u32.u64 %0, t; }" : "=r"(a) : "l"(p));
    return a;
}
__device__ __forceinline__ void cvt_hilo(float a, unsigned short& h, unsigned short& l) {
    __nv_bfloat16 bh = __float2bfloat16(a);
    float r = a - __bfloat162float(bh);
    __nv_bfloat16 bl = __float2bfloat16(r);
    h = __bfloat16_as_ushort(bh);
    l = __bfloat16_as_ushort(bl);
}
__device__ __forceinline__ void ldm_x4(unsigned int* r, unsigned int addr) {
    asm volatile("ldmatrix.sync.aligned.m8n8.x4.shared.b16 {%0,%1,%2,%3}, [%4];"
                 : "=r"(r[0]), "=r"(r[1]), "=r"(r[2]), "=r"(r[3]) : "r"(addr));
}
__device__ __forceinline__ void ldm_x4t(unsigned int* r, unsigned int addr) {
    asm volatile("ldmatrix.sync.aligned.m8n8.x4.trans.shared.b16 {%0,%1,%2,%3}, [%4];"
                 : "=r"(r[0]), "=r"(r[1]), "=r"(r[2]), "=r"(r[3]) : "r"(addr));
}
__device__ __forceinline__ void mma_bf16(float* c, const unsigned int* a, const unsigned int* b) {
    asm volatile(
        "mma.sync.aligned.m16n8k16.row.col.f32.bf16.bf16.f32 "
        "{%0,%1,%2,%3}, {%4,%5,%6,%7}, {%8,%9}, {%0,%1,%2,%3};"
        : "+f"(c[0]), "+f"(c[1]), "+f"(c[2]), "+f"(c[3])
        : "r"(a[0]), "r"(a[1]), "r"(a[2]), "r"(a[3]), "r"(b[0]), "r"(b[1]));
}

// ---------------- unified init + x copy ----------------
__global__ __launch_bounds__(256) void k_initx(const float* __restrict__ x) {
    int i = blockIdx.x * blockDim.x + threadIdx.x;
    if (i < Nn * 16) {
        int n = i >> 4, j = i & 15;
        g_hcat1[n * 64 + j] = x[i];
    }
    if (i < Nn) { g_deg[i] = 0.f; g_cnt[i] = 0; g_cur[i] = 0; }
    if (i < 1024) g_stats[i] = 0.f;
    if (i < 768) g_stats2[i] = 0.f;
    if (i < Gg * 256) { g_pmax[i] = 0; g_pmin[i] = 0x7F800000; }
}

// ---------------- graph preprocessing ----------------
__global__ __launch_bounds__(256) void k_deg_hist(const int* __restrict__ col,
                                                  const float* __restrict__ ea) {
    int e = blockIdx.x * blockDim.x + threadIdx.x;
    if (e >= Ee) return;
    int c = col[e];
    atomicAdd(&g_deg[c], ea[e]);
    atomicAdd(&g_cnt[c], 1);
}

__global__ __launch_bounds__(256) void k_scan() {
    __shared__ int ss[256];
    const int CH = (Nn + 255) / 256;
    int t = threadIdx.x;
    int base = t * CH;
    int s = 0;
    for (int i = 0; i < CH; i++) { int idx = base + i; if (idx < Nn) s += g_cnt[idx]; }
    ss[t] = s;
    __syncthreads();
    int own = s;
    for (int o = 1; o < 256; o <<= 1) {
        int v = (t >= o) ? ss[t - o] : 0;
        __syncthreads();
        ss[t] += v;
        __syncthreads();
    }
    int run = ss[t] - own;
    for (int i = 0; i < CH; i++) {
        int idx = base + i;
        if (idx < Nn) { g_off[idx] = run; run += g_cnt[idx]; }
    }
}

__global__ __launch_bounds__(256) void k_scatter(const int* __restrict__ row,
                                                 const int* __restrict__ col,
                                                 const float* __restrict__ ea) {
    int e = blockIdx.x * blockDim.x + threadIdx.x;
    if (e >= Ee) return;
    int r = row[e], c = col[e];
    float dr = g_deg[r], dc = g_deg[c];
    float ir = dr > 0.f ? rsqrtf(dr) : 0.f;
    float ic = dc > 0.f ? rsqrtf(dc) : 0.f;
    float w = ir * ea[e] * ic;
    int p = g_off[c] + atomicAdd(&g_cur[c], 1);
    g_rowS[p] = r;
    g_wS[p] = w;
}

// CSR gather propagation
template <int TPN>
__global__ __launch_bounds__(256) void k_prop(float* __restrict__ hbase, int stride,
                                              int so, int dofs) {
    int gid = blockIdx.x * blockDim.x + threadIdx.x;
    int node = gid / TPN;
    int part = gid % TPN;
    if (node >= Nn) return;
    int s = g_off[node];
    int e = s + g_cnt[node];
    float4 acc = make_float4(0.f, 0.f, 0.f, 0.f);
    int so4 = so + part * 4;
    for (int i = s; i < e; i++) {
        int r = __ldg(&g_rowS[i]);
        float w = __ldg(&g_wS[i]);
        const float4 v = *reinterpret_cast<const float4*>(hbase + (size_t)r * stride + so4);
        acc.x = fmaf(w, v.x, acc.x);
        acc.y = fmaf(w, v.y, acc.y);
        acc.z = fmaf(w, v.z, acc.z);
        acc.w = fmaf(w, v.w, acc.w);
    }
    *reinterpret_cast<float4*>(hbase + (size_t)node * stride + dofs + part * 4) = acc;
}

// ---------------- all weights -> bf16 hi/lo images (one launch) ----------------
__global__ __launch_bounds__(256) void k_prepWbf_all(const float* __restrict__ W2,
                                                     const float* __restrict__ Wl,
                                                     const float* __restrict__ W1) {
    int idx = blockIdx.x * blockDim.x + threadIdx.x;
    unsigned short h, l;
    if (idx < 65536) {
        cvt_hilo(W2[idx], h, l);
        g_W2bh[idx] = h; g_W2bl[idx] = l;
    } else if (idx < 131072) {
        int j = idx - 65536;
        cvt_hilo(Wl[j], h, l);
        g_Wlbh[j] = h; g_Wlbl[j] = l;
    } else if (idx < 139264) {
        int j = idx - 131072;
        cvt_hilo(W1[j], h, l);
        g_W1bh[j] = h; g_W1bl[j] = l;
    }
}

// =====================================================================
// shared smem layout constants for mma kernels
// =====================================================================
#define MMA_A_HI 0
#define MMA_A_LO 18432
#define MMA_B_HI 36864
#define MMA_B_LO 54272
#define MMA_SMEM 71680
#define STG_RED  67584

// =====================================================================
// conv2 GEMM via mma.sync bf16 split + staged-stats epilogue (R15 winner)
// =====================================================================
__global__ __launch_bounds__(256) void k_gemm_conv2_mma(const float* __restrict__ A,
                                                        const float* __restrict__ bias,
                                                        float* __restrict__ C,
                                                        float* __restrict__ sS,
                                                        float* __restrict__ sQ) {
    extern __shared__ char smem[];
    unsigned int sb = smem_u32(smem);
    int tid = threadIdx.x;
    int lane = tid & 31;
    int wid = tid >> 5;
    int warp_m = wid & 3;
    int warp_n = wid >> 2;
    int row0 = blockIdx.x * 128;

    float acc[2][8][4];
#pragma unroll
    for (int mt = 0; mt < 2; mt++)
#pragma unroll
        for (int nt = 0; nt < 8; nt++)
#pragma unroll
            for (int j = 0; j < 4; j++) acc[mt][nt][j] = 0.f;

    int col4 = tid & 15;
    int rbase = tid >> 4;

    for (int c = 0; c < 8; c++) {
        int kbase = c * 64;
#pragma unroll
        for (int i = 0; i < 8; i++) {
            int r = rbase + i * 16;
            int grow = row0 + r;
            float4 v = make_float4(0.f, 0.f, 0.f, 0.f);
            if (grow < Nn)
                v = *reinterpret_cast<const float4*>(&A[(size_t)grow * 512 + kbase + col4 * 4]);
            unsigned short h0, l0, h1, l1, h2, l2, h3, l3;
            cvt_hilo(v.x, h0, l0);
            cvt_hilo(v.y, h1, l1);
            cvt_hilo(v.z, h2, l2);
            cvt_hilo(v.w, h3, l3);
            int ob = r * 144 + col4 * 8;
            *reinterpret_cast<uint2*>(smem + MMA_A_HI + ob) =
                make_uint2((unsigned)h0 | ((unsigned)h1 << 16), (unsigned)h2 | ((unsigned)h3 << 16));
            *reinterpret_cast<uint2*>(smem + MMA_A_LO + ob) =
                make_uint2((unsigned)l0 | ((unsigned)l1 << 16), (unsigned)l2 | ((unsigned)l3 << 16));
        }
#pragma unroll
        for (int j = 0; j < 4; j++) {
            int idx = tid + j * 256;
            int kr = idx >> 4, c8 = idx & 15;
            int ob = kr * 272 + c8 * 16;
            *reinterpret_cast<uint4*>(smem + MMA_B_HI + ob) =
                *reinterpret_cast<const uint4*>(&g_W2bh[(kbase + kr) * 128 + c8 * 8]);
            *reinterpret_cast<uint4*>(smem + MMA_B_LO + ob) =
                *reinterpret_cast<const uint4*>(&g_W2bl[(kbase + kr) * 128 + c8 * 8]);
        }
        __syncthreads();

#pragma unroll
        for (int ks = 0; ks < 4; ks++) {
            unsigned int Ah[2][4], Al[2][4], Bf[4][4];
            int arow = (lane & 15);
            int acolb = ks * 32 + (lane >> 4) * 16;
#pragma unroll
            for (int mt = 0; mt < 2; mt++) {
                int m0 = warp_m * 32 + mt * 16;
                unsigned int aoff = (unsigned)((m0 + arow) * 144 + acolb);
                ldm_x4(Ah[mt], sb + MMA_A_HI + aoff);
                ldm_x4(Al[mt], sb + MMA_A_LO + aoff);
            }
            int brow = ks * 16 + (lane & 15);
#pragma unroll
            for (int p = 0; p < 4; p++) {
                unsigned int boff = (unsigned)(brow * 272 + (warp_n * 64 + p * 16 + (lane >> 4) * 8) * 2);
                ldm_x4t(Bf[p], sb + MMA_B_HI + boff);
            }
#pragma unroll
            for (int mt = 0; mt < 2; mt++)
#pragma unroll
                for (int p = 0; p < 4; p++) {
                    mma_bf16(acc[mt][2 * p],     Ah[mt], &Bf[p][0]);
                    mma_bf16(acc[mt][2 * p + 1], Ah[mt], &Bf[p][2]);
                    mma_bf16(acc[mt][2 * p],     Al[mt], &Bf[p][0]);
                    mma_bf16(acc[mt][2 * p + 1], Al[mt], &Bf[p][2]);
                }
#pragma unroll
            for (int p = 0; p < 4; p++) {
                unsigned int boff = (unsigned)(brow * 272 + (warp_n * 64 + p * 16 + (lane >> 4) * 8) * 2);
                ldm_x4t(Bf[p], sb + MMA_B_LO + boff);
            }
#pragma unroll
            for (int mt = 0; mt < 2; mt++)
#pragma unroll
                for (int p = 0; p < 4; p++) {
                    mma_bf16(acc[mt][2 * p],     Ah[mt], &Bf[p][0]);
                    mma_bf16(acc[mt][2 * p + 1], Ah[mt], &Bf[p][2]);
                }
        }
        __syncthreads();
    }

    float* stg = reinterpret_cast<float*>(smem);
    float* red = reinterpret_cast<float*>(smem + STG_RED);
    red[tid] = 0.f;
#pragma unroll
    for (int mt = 0; mt < 2; mt++) {
        int rloc = warp_m * 32 + mt * 16 + (lane >> 2);
        int r0 = row0 + rloc;
#pragma unroll
        for (int nt = 0; nt < 8; nt++) {
            int cloc = warp_n * 64 + nt * 8 + (lane & 3) * 2;
            float b0 = __ldg(&bias[cloc]), b1 = __ldg(&bias[cloc + 1]);
            float o0 = fmaxf(acc[mt][nt][0] + b0, 0.f);
            float o1 = fmaxf(acc[mt][nt][1] + b1, 0.f);
            float o2 = fmaxf(acc[mt][nt][2] + b0, 0.f);
            float o3 = fmaxf(acc[mt][nt][3] + b1, 0.f);
            stg[rloc * 132 + cloc]           = o0;
            stg[rloc * 132 + cloc + 1]       = o1;
            stg[(rloc + 8) * 132 + cloc]     = o2;
            stg[(rloc + 8) * 132 + cloc + 1] = o3;
            if (r0 < Nn)
                *reinterpret_cast<float2*>(&C[(size_t)r0 * 256 + cloc]) = make_float2(o0, o1);
            if (r0 + 8 < Nn)
                *reinterpret_cast<float2*>(&C[(size_t)(r0 + 8) * 256 + cloc]) = make_float2(o2, o3);
        }
    }
    __syncthreads();

    int ty = tid >> 4, tx = tid & 15;
    float s[8], q[8];
#pragma unroll
    for (int j = 0; j < 8; j++) { s[j] = 0.f; q[j] = 0.f; }
#pragma unroll
    for (int i = 0; i < 8; i++) {
        int row = row0 + ty * 8 + i;
        if (row >= Nn) continue;
#pragma unroll
        for (int j = 0; j < 8; j++) {
            float v = stg[(ty * 8 + i) * 132 + tx * 8 + j];
            s[j] += v;
            q[j] = fmaf(v, v, q[j]);
        }
    }
#pragma unroll
    for (int j = 0; j < 8; j++) {
        atomicAdd(&red[tx * 8 + j], s[j]);
        atomicAdd(&red[128 + tx * 8 + j], q[j]);
    }
    __syncthreads();
    if (tid < 128) atomicAdd(&sS[tid], red[tid]);
    else           atomicAdd(&sQ[tid - 128], red[tid]);
}

// =====================================================================
// conv1 GEMM via mma.sync bf16 split (R13 winner, unchanged)
// =====================================================================
#define CMA_RED 67584
#define CMA_SMEM 71680

__global__ __launch_bounds__(256) void k_gemm_conv1_mma(const float* __restrict__ A,
                                                        const float* __restrict__ bias,
                                                        float* __restrict__ C,
                                                        float* __restrict__ sS,
                                                        float* __restrict__ sQ) {
    extern __shared__ char smem[];
    unsigned int sb = smem_u32(smem);
    int tid = threadIdx.x;
    int lane = tid & 31;
    int wid = tid >> 5;
    int warp_m = wid & 3;
    int warp_n = wid >> 2;
    int row0 = blockIdx.x * 128;

    float acc[2][8][4];
#pragma unroll
    for (int mt = 0; mt < 2; mt++)
#pragma unroll
        for (int nt = 0; nt < 8; nt++)
#pragma unroll
            for (int j = 0; j < 4; j++) acc[mt][nt][j] = 0.f;

    int col4 = tid & 15;
    int rbase = tid >> 4;

#pragma unroll
    for (int i = 0; i < 8; i++) {
        int r = rbase + i * 16;
        int grow = row0 + r;
        float4 v = make_float4(0.f, 0.f, 0.f, 0.f);
        if (grow < Nn)
            v = *reinterpret_cast<const float4*>(&A[(size_t)grow * 64 + col4 * 4]);
        unsigned short h0, l0, h1, l1, h2, l2, h3, l3;
        cvt_hilo(v.x, h0, l0);
        cvt_hilo(v.y, h1, l1);
        cvt_hilo(v.z, h2, l2);
        cvt_hilo(v.w, h3, l3);
        int ob = r * 144 + col4 * 8;
        *reinterpret_cast<uint2*>(smem + MMA_A_HI + ob) =
            make_uint2((unsigned)h0 | ((unsigned)h1 << 16), (unsigned)h2 | ((unsigned)h3 << 16));
        *reinterpret_cast<uint2*>(smem + MMA_A_LO + ob) =
            make_uint2((unsigned)l0 | ((unsigned)l1 << 16), (unsigned)l2 | ((unsigned)l3 << 16));
    }
#pragma unroll
    for (int j = 0; j < 4; j++) {
        int idx = tid + j * 256;
        int kr = idx >> 4, c8 = idx & 15;
        int ob = kr * 272 + c8 * 16;
        *reinterpret_cast<uint4*>(smem + MMA_B_HI + ob) =
            *reinterpret_cast<const uint4*>(&g_W1bh[kr * 128 + c8 * 8]);
        *reinterpret_cast<uint4*>(smem + MMA_B_LO + ob) =
            *reinterpret_cast<const uint4*>(&g_W1bl[kr * 128 + c8 * 8]);
    }
    __syncthreads();

#pragma unroll
    for (int ks = 0; ks < 4; ks++) {
        unsigned int Ah[2][4], Al[2][4], Bf[4][4];
        int arow = (lane & 15);
        int acolb = ks * 32 + (lane >> 4) * 16;
#pragma unroll
        for (int mt = 0; mt < 2; mt++) {
            int m0 = warp_m * 32 + mt * 16;
            unsigned int aoff = (unsigned)((m0 + arow) * 144 + acolb);
            ldm_x4(Ah[mt], sb + MMA_A_HI + aoff);
            ldm_x4(Al[mt], sb + MMA_A_LO + aoff);
        }
        int brow = ks * 16 + (lane & 15);
#pragma unroll
        for (int p = 0; p < 4; p++) {
            unsigned int boff = (unsigned)(brow * 272 + (warp_n * 64 + p * 16 + (lane >> 4) * 8) * 2);
            ldm_x4t(Bf[p], sb + MMA_B_HI + boff);
        }
#pragma unroll
        for (int mt = 0; mt < 2; mt++)
#pragma unroll
            for (int p = 0; p < 4; p++) {
                mma_bf16(acc[mt][2 * p],     Ah[mt], &Bf[p][0]);
                mma_bf16(acc[mt][2 * p + 1], Ah[mt], &Bf[p][2]);
                mma_bf16(acc[mt][2 * p],     Al[mt], &Bf[p][0]);
                mma_bf16(acc[mt][2 * p + 1], Al[mt], &Bf[p][2]);
            }
#pragma unroll
        for (int p = 0; p < 4; p++) {
            unsigned int boff = (unsigned)(brow * 272 + (warp_n * 64 + p * 16 + (lane >> 4) * 8) * 2);
            ldm_x4t(Bf[p], sb + MMA_B_LO + boff);
        }
#pragma unroll
        for (int mt = 0; mt < 2; mt++)
#pragma unroll
            for (int p = 0; p < 4; p++) {
                mma_bf16(acc[mt][2 * p],     Ah[mt], &Bf[p][0]);
                mma_bf16(acc[mt][2 * p + 1], Ah[mt], &Bf[p][2]);
            }
    }
    __syncthreads();

    float* stg = reinterpret_cast<float*>(smem);
    float* red = reinterpret_cast<float*>(smem + CMA_RED);
    red[tid] = 0.f;
#pragma unroll
    for (int mt = 0; mt < 2; mt++) {
        int rloc = warp_m * 32 + mt * 16 + (lane >> 2);
        int r0 = row0 + rloc;
#pragma unroll
        for (int nt = 0; nt < 8; nt++) {
            int cloc = warp_n * 64 + nt * 8 + (lane & 3) * 2;
            float b0 = __ldg(&bias[cloc]), b1 = __ldg(&bias[cloc + 1]);
            float o0 = fmaxf(acc[mt][nt][0] + b0, 0.f);
            float o1 = fmaxf(acc[mt][nt][1] + b1, 0.f);
            float o2 = fmaxf(acc[mt][nt][2] + b0, 0.f);
            float o3 = fmaxf(acc[mt][nt][3] + b1, 0.f);
            stg[rloc * 132 + cloc]           = o0;
            stg[rloc * 132 + cloc + 1]       = o1;
            stg[(rloc + 8) * 132 + cloc]     = o2;
            stg[(rloc + 8) * 132 + cloc + 1] = o3;
            if (r0 < Nn)
                *reinterpret_cast<float2*>(&C[(size_t)r0 * 256 + cloc]) = make_float2(o0, o1);
            if (r0 + 8 < Nn)
                *reinterpret_cast<float2*>(&C[(size_t)(r0 + 8) * 256 + cloc]) = make_float2(o2, o3);
        }
    }
    __syncthreads();

    int ty = tid >> 4, tx = tid & 15;
    float s[8], q[8];
#pragma unroll
    for (int j = 0; j < 8; j++) { s[j] = 0.f; q[j] = 0.f; }
#pragma unroll
    for (int i = 0; i < 8; i++) {
        int row = row0 + ty * 8 + i;
        if (row >= Nn) continue;
#pragma unroll
        for (int j = 0; j < 8; j++) {
            float v = stg[(ty * 8 + i) * 132 + tx * 8 + j];
            s[j] += v;
            q[j] = fmaf(v, v, q[j]);
        }
    }
#pragma unroll
    for (int j = 0; j < 8; j++) {
        atomicAdd(&red[tx * 8 + j], s[j]);
        atomicAdd(&red[128 + tx * 8 + j], q[j]);
    }
    __syncthreads();
    if (tid < 128) atomicAdd(&sS[tid], red[tid]);
    else           atomicAdd(&sQ[tid - 128], red[tid]);
}

// =====================================================================
// lin1 GEMM via mma.sync bf16 split; BN params computed inline from raw
// stats (replaces k_bnparam dependency).
// =====================================================================
#define LMA_STAGE 0
#define LMA_RED   67584
#define LMA_PMAX  68608
#define LMA_PMIN  70656
#define LMA_SMEM  72704

__global__ __launch_bounds__(256) void k_gemm_lin_mma(const float* __restrict__ A,
                                                      const float* __restrict__ bias,
                                                      const int* __restrict__ batch,
                                                      const float* __restrict__ gamma1,
                                                      const float* __restrict__ beta1,
                                                      const float* __restrict__ gamma2,
                                                      const float* __restrict__ beta2,
                                                      float* __restrict__ sS,
                                                      float* __restrict__ sQ) {
    extern __shared__ char smem[];
    __shared__ float sbn_sc[256], sbn_sh[256];
    unsigned int sb = smem_u32(smem);
    int tid = threadIdx.x;
    int lane = tid & 31;
    int wid = tid >> 5;
    int warp_m = wid & 3;
    int warp_n = wid >> 2;
    int row0 = blockIdx.x * 128;
    int col0 = blockIdx.y * 128;
    {
        float m, var, ga, be;
        if (tid < 128) {
            m = g_stats[tid] * (1.f / Nn);
            var = g_stats[128 + tid] * (1.f / Nn) - m * m;
            ga = gamma1[tid]; be = beta1[tid];
        } else {
            int c = tid - 128;
            m = g_stats[256 + c] * (1.f / Nn);
            var = g_stats[384 + c] * (1.f / Nn) - m * m;
            ga = gamma2[c]; be = beta2[c];
        }
        float sc = ga * rsqrtf(var + EPSb);
        sbn_sc[tid] = sc;
        sbn_sh[tid] = be - m * sc;
    }
    __syncthreads();

    float acc[2][8][4];
#pragma unroll
    for (int mt = 0; mt < 2; mt++)
#pragma unroll
        for (int nt = 0; nt < 8; nt++)
#pragma unroll
            for (int j = 0; j < 4; j++) acc[mt][nt][j] = 0.f;

    int col4 = tid & 15;
    int rbase = tid >> 4;

    for (int c = 0; c < 4; c++) {
        int kbase = c * 64;
#pragma unroll
        for (int i = 0; i < 8; i++) {
            int r = rbase + i * 16;
            int grow = row0 + r;
            float4 v = make_float4(0.f, 0.f, 0.f, 0.f);
            if (grow < Nn) {
                v = *reinterpret_cast<const float4*>(&A[(size_t)grow * 256 + kbase + col4 * 4]);
                int kc = kbase + col4 * 4;
                v.x = fmaf(v.x, sbn_sc[kc],     sbn_sh[kc]);
                v.y = fmaf(v.y, sbn_sc[kc + 1], sbn_sh[kc + 1]);
                v.z = fmaf(v.z, sbn_sc[kc + 2], sbn_sh[kc + 2]);
                v.w = fmaf(v.w, sbn_sc[kc + 3], sbn_sh[kc + 3]);
            }
            unsigned short h0, l0, h1, l1, h2, l2, h3, l3;
            cvt_hilo(v.x, h0, l0);
            cvt_hilo(v.y, h1, l1);
            cvt_hilo(v.z, h2, l2);
            cvt_hilo(v.w, h3, l3);
            int ob = r * 144 + col4 * 8;
            *reinterpret_cast<uint2*>(smem + MMA_A_HI + ob) =
                make_uint2((unsigned)h0 | ((unsigned)h1 << 16), (unsigned)h2 | ((unsigned)h3 << 16));
            *reinterpret_cast<uint2*>(smem + MMA_A_LO + ob) =
                make_uint2((unsigned)l0 | ((unsigned)l1 << 16), (unsigned)l2 | ((unsigned)l3 << 16));
        }
#pragma unroll
        for (int j = 0; j < 4; j++) {
            int idx = tid + j * 256;
            int kr = idx >> 4, c8 = idx & 15;
            int ob = kr * 272 + c8 * 16;
            *reinterpret_cast<uint4*>(smem + MMA_B_HI + ob) =
                *reinterpret_cast<const uint4*>(&g_Wlbh[(kbase + kr) * 256 + col0 + c8 * 8]);
            *reinterpret_cast<uint4*>(smem + MMA_B_LO + ob) =
                *reinterpret_cast<const uint4*>(&g_Wlbl[(kbase + kr) * 256 + col0 + c8 * 8]);
        }
        __syncthreads();

#pragma unroll
        for (int ks = 0; ks < 4; ks++) {
            unsigned int Ah[2][4], Al[2][4], Bf[4][4];
            int arow = (lane & 15);
            int acolb = ks * 32 + (lane >> 4) * 16;
#pragma unroll
            for (int mt = 0; mt < 2; mt++) {
                int m0 = warp_m * 32 + mt * 16;
                unsigned int aoff = (unsigned)((m0 + arow) * 144 + acolb);
                ldm_x4(Ah[mt], sb + MMA_A_HI + aoff);
                ldm_x4(Al[mt], sb + MMA_A_LO + aoff);
            }
            int brow = ks * 16 + (lane & 15);
#pragma unroll
            for (int p = 0; p < 4; p++) {
                unsigned int boff = (unsigned)(brow * 272 + (warp_n * 64 + p * 16 + (lane >> 4) * 8) * 2);
                ldm_x4t(Bf[p], sb + MMA_B_HI + boff);
            }
#pragma unroll
            for (int mt = 0; mt < 2; mt++)
#pragma unroll
                for (int p = 0; p < 4; p++) {
                    mma_bf16(acc[mt][2 * p],     Ah[mt], &Bf[p][0]);
                    mma_bf16(acc[mt][2 * p + 1], Ah[mt], &Bf[p][2]);
                    mma_bf16(acc[mt][2 * p],     Al[mt], &Bf[p][0]);
                    mma_bf16(acc[mt][2 * p + 1], Al[mt], &Bf[p][2]);
                }
#pragma unroll
            for (int p = 0; p < 4; p++) {
                unsigned int boff = (unsigned)(brow * 272 + (warp_n * 64 + p * 16 + (lane >> 4) * 8) * 2);
                ldm_x4t(Bf[p], sb + MMA_B_LO + boff);
            }
#pragma unroll
            for (int mt = 0; mt < 2; mt++)
#pragma unroll
                for (int p = 0; p < 4; p++) {
                    mma_bf16(acc[mt][2 * p],     Ah[mt], &Bf[p][0]);
                    mma_bf16(acc[mt][2 * p + 1], Ah[mt], &Bf[p][2]);
                }
        }
        __syncthreads();
    }

    float* stg = reinterpret_cast<float*>(smem + LMA_STAGE);
#pragma unroll
    for (int mt = 0; mt < 2; mt++) {
        int rloc = warp_m * 32 + mt * 16 + (lane >> 2);
#pragma unroll
        for (int nt = 0; nt < 8; nt++) {
            int cloc = warp_n * 64 + nt * 8 + (lane & 3) * 2;
            float b0 = __ldg(&bias[col0 + cloc]), b1 = __ldg(&bias[col0 + cloc + 1]);
            stg[rloc * 132 + cloc]           = fmaxf(acc[mt][nt][0] + b0, 0.f);
            stg[rloc * 132 + cloc + 1]       = fmaxf(acc[mt][nt][1] + b1, 0.f);
            stg[(rloc + 8) * 132 + cloc]     = fmaxf(acc[mt][nt][2] + b0, 0.f);
            stg[(rloc + 8) * 132 + cloc + 1] = fmaxf(acc[mt][nt][3] + b1, 0.f);
        }
    }
    float* red  = reinterpret_cast<float*>(smem + LMA_RED);
    int*  pmaxS = reinterpret_cast<int*>(smem + LMA_PMAX);
    int*  pminS = reinterpret_cast<int*>(smem + LMA_PMIN);
    red[tid] = 0.f;
    pmaxS[tid] = 0; pmaxS[tid + 256] = 0;
    pminS[tid] = 0x7F800000; pminS[tid + 256] = 0x7F800000;
    __syncthreads();

    int ty = tid >> 4, tx = tid & 15;
    int gbase = batch[row0];
    float s[8], q[8], vmx[8], vmn[8];
#pragma unroll
    for (int j = 0; j < 8; j++) { s[j] = 0.f; q[j] = 0.f; vmx[j] = 0.f; vmn[j] = __int_as_float(0x7F800000); }
    int cur_slot = -1;
#pragma unroll
    for (int i = 0; i < 8; i++) {
        int row = row0 + ty * 8 + i;
        if (row >= Nn) continue;
        int slot = batch[row] - gbase;
        if (slot != cur_slot) {
            if (cur_slot >= 0) {
#pragma unroll
                for (int j = 0; j < 8; j++) {
                    int c = tx * 8 + j;
                    if (cur_slot < 4) {
                        atomicMax(&pmaxS[cur_slot * 128 + c], __float_as_int(vmx[j]));
                        atomicMin(&pminS[cur_slot * 128 + c], __float_as_int(vmn[j]));
                    } else {
                        atomicMax(&g_pmax[(gbase + cur_slot) * 256 + col0 + c], __float_as_int(vmx[j]));
                        atomicMin(&g_pmin[(gbase + cur_slot) * 256 + col0 + c], __float_as_int(vmn[j]));
                    }
                    vmx[j] = 0.f; vmn[j] = __int_as_float(0x7F800000);
                }
            }
            cur_slot = slot;
        }
#pragma unroll
        for (int j = 0; j < 8; j++) {
            float v = stg[(ty * 8 + i) * 132 + tx * 8 + j];
            s[j] += v;
            q[j] = fmaf(v, v, q[j]);
            vmx[j] = fmaxf(vmx[j], v);
            vmn[j] = fminf(vmn[j], v);
        }
    }
    if (cur_slot >= 0) {
#pragma unroll
        for (int j = 0; j < 8; j++) {
            int c = tx * 8 + j;
            if (cur_slot < 4) {
                atomicMax(&pmaxS[cur_slot * 128 + c], __float_as_int(vmx[j]));
                atomicMin(&pminS[cur_slot * 128 + c], __float_as_int(vmn[j]));
            } else {
                atomicMax(&g_pmax[(gbase + cur_slot) * 256 + col0 + c], __float_as_int(vmx[j]));
                atomicMin(&g_pmin[(gbase + cur_slot) * 256 + col0 + c], __float_as_int(vmn[j]));
            }
        }
    }
#pragma unroll
    for (int j = 0; j < 8; j++) {
        atomicAdd(&red[tx * 8 + j], s[j]);
        atomicAdd(&red[128 + tx * 8 + j], q[j]);
    }
    __syncthreads();
    if (tid < 128) {
        atomicAdd(&sS[col0 + tid], red[tid]);
#pragma unroll
        for (int sl = 0; sl < 4; sl++) {
            int g = gbase + sl;
            if (g < Gg) {
                atomicMax(&g_pmax[g * 256 + col0 + tid], pmaxS[sl * 128 + tid]);
                atomicMin(&g_pmin[g * 256 + col0 + tid], pminS[sl * 128 + tid]);
            }
        }
    } else {
        atomicAdd(&sQ[col0 + tid - 128], red[tid]);
    }
}

// ---------------- h0 (BN1 params computed per block from raw stats) ----------------
__global__ __launch_bounds__(256) void k_h0(const float* __restrict__ gamma1,
                                            const float* __restrict__ beta1) {
    __shared__ float ssc[128], ssh[128];
    int t = threadIdx.x;
    if (t < 128) {
        float m = g_stats[t] * (1.f / Nn);
        float var = g_stats[128 + t] * (1.f / Nn) - m * m;
        float sc = gamma1[t] * rsqrtf(var + EPSb);
        ssc[t] = sc;
        ssh[t] = beta1[t] - m * sc;
    }
    __syncthreads();
    int idx = blockIdx.x * blockDim.x + t;
    if (idx >= Nn * 32) return;
    int n = idx >> 5, c4 = (idx & 31) * 4;
    float4 v = *reinterpret_cast<const float4*>(&g_xcat[(size_t)n * 256 + c4]);
    float4 o;
    o.x = fmaf(v.x, ssc[c4],     ssh[c4]);
    o.y = fmaf(v.y, ssc[c4 + 1], ssh[c4 + 1]);
    o.z = fmaf(v.z, ssc[c4 + 2], ssh[c4 + 2]);
    o.w = fmaf(v.w, ssc[c4 + 3], ssh[c4 + 3]);
    *reinterpret_cast<float4*>(&g_hcat2[(size_t)n * 512 + c4]) = o;
}

// ---------------- merged head: 3 kernels (R16 winners) ----------------
__global__ __launch_bounds__(256) void k_head1(const float* __restrict__ gammal,
                                               const float* __restrict__ betal,
                                               const float* __restrict__ Wf1,
                                               const float* __restrict__ bf1) {
    __shared__ float ps[256];
    int g = blockIdx.x, c = threadIdx.x;
    float m = g_stats[512 + c] * (1.f / Nn);
    float var = g_stats[768 + c] * (1.f / Nn) - m * m;
    float sc = gammal[c] * rsqrtf(var + EPSb);
    float sh = betal[c] - m * sc;
    float vmax = __int_as_float(g_pmax[g * 256 + c]);
    float vmin = __int_as_float(g_pmin[g * 256 + c]);
    ps[c] = (sc >= 0.f ? sc * vmax : sc * vmin) + sh;
    __syncthreads();
    float acc = bf1[c];
    for (int k = 0; k < 256; k++) acc = fmaf(ps[k], Wf1[k * 256 + c], acc);
    float o = fmaxf(acc, 0.f);
    g_f1[g * 256 + c] = o;
    atomicAdd(&g_stats2[c], o);
    atomicAdd(&g_stats2[256 + c], o * o);
}

__global__ __launch_bounds__(128) void k_head2(const float* __restrict__ gammaf1,
                                               const float* __restrict__ betaf1,
                                               const float* __restrict__ Wf2,
                                               const float* __restrict__ bf2) {
    __shared__ float fs[256];
    int g = blockIdx.x, t = threadIdx.x;
    for (int j = t; j < 256; j += 128) {
        float m = g_stats2[j] * (1.f / Gg);
        float var = g_stats2[256 + j] * (1.f / Gg) - m * m;
        float sc = gammaf1[j] * rsqrtf(var + EPSb);
        float sh = betaf1[j] - m * sc;
        fs[j] = fmaf(g_f1[g * 256 + j], sc, sh);
    }
    __syncthreads();
    float acc = bf2[t];
    for (int k = 0; k < 256; k++) acc = fmaf(fs[k], Wf2[k * 128 + t], acc);
    float o = fmaxf(acc, 0.f);
    g_f2[g * 128 + t] = o;
    atomicAdd(&g_stats2[512 + t], o);
    atomicAdd(&g_stats2[640 + t], o * o);
}

__global__ __launch_bounds__(128) void k_logits(const float* __restrict__ gammaf2,
                                                const float* __restrict__ betaf2,
                                                const float* __restrict__ Wf3,
                                                const float* __restrict__ bf3,
                                                float* __restrict__ out) {
    __shared__ float fs[128], sl[64];
    __shared__ float s_m, s_l;
    int g = blockIdx.x, t = threadIdx.x;
    {
        float m = g_stats2[512 + t] * (1.f / Gg);
        float var = g_stats2[640 + t] * (1.f / Gg) - m * m;
        float sc = gammaf2[t] * rsqrtf(var + EPSb);
        float sh = betaf2[t] - m * sc;
        fs[t] = fmaf(g_f2[g * 128 + t], sc, sh);
    }
    __syncthreads();
    if (t < Cc) {
        float acc = bf3[t];
        for (int k = 0; k < 128; k++) acc = fmaf(fs[k], Wf3[k * Cc + t], acc);
        sl[t] = acc;
    }
    __syncthreads();
    if (t == 0) {
        float m = -INFINITY;
        for (int i = 0; i < Cc; i++) m = fmaxf(m, sl[i]);
        float s = 0.f;
        for (int i = 0; i < Cc; i++) s += expf(sl[i] - m);
        s_m = m;
        s_l = logf(s);
    }
    __syncthreads();
    if (t < Cc) out[g * Cc + t] = sl[t] - s_m - s_l;
}

// ---------------- launch ----------------
extern "C" void kernel_launch(void* const* d_in, const int* in_sizes, int n_in,
                              void* d_out, int out_size) {
    const float* x      = (const float*)d_in[0];
    const int*   ei     = (const int*)d_in[1];
    const float* ea     = (const float*)d_in[2];
    const int*   batch  = (const int*)d_in[3];
    const float* W1     = (const float*)d_in[4];
    const float* b1     = (const float*)d_in[5];
    const float* gamma1 = (const float*)d_in[6];
    const float* beta1  = (const float*)d_in[7];
    const float* W2     = (const float*)d_in[8];
    const float* b2     = (const float*)d_in[9];
    const float* gamma2 = (const float*)d_in[10];
    const float* beta2  = (const float*)d_in[11];
    const float* Wl     = (const float*)d_in[12];
    const float* bl     = (const float*)d_in[13];
    const float* gammal = (const float*)d_in[14];
    const float* betal  = (const float*)d_in[15];
    const float* Wf1    = (const float*)d_in[16];
    const float* bf1    = (const float*)d_in[17];
    const float* gammaf1= (const float*)d_in[18];
    const float* betaf1 = (const float*)d_in[19];
    const float* Wf2    = (const float*)d_in[20];
    const float* bf2    = (const float*)d_in[21];
    const float* gammaf2= (const float*)d_in[22];
    const float* betaf2 = (const float*)d_in[23];
    const float* Wf3    = (const float*)d_in[24];
    const float* bf3    = (const float*)d_in[25];
    const int* row = ei;
    const int* col = ei + Ee;
    float* out = (float*)d_out;

    float *p_hcat1, *p_hcat2, *p_xcat, *p_stats;
    cudaGetSymbolAddress((void**)&p_hcat1, g_hcat1);
    cudaGetSymbolAddress((void**)&p_hcat2, g_hcat2);
    cudaGetSymbolAddress((void**)&p_xcat, g_xcat);
    cudaGetSymbolAddress((void**)&p_stats, g_stats);

    cudaFuncSetAttribute(k_gemm_conv2_mma, cudaFuncAttributeMaxDynamicSharedMemorySize,
                         MMA_SMEM);
    cudaFuncSetAttribute(k_gemm_conv1_mma, cudaFuncAttributeMaxDynamicSharedMemorySize,
                         CMA_SMEM);
    cudaFuncSetAttribute(k_gemm_lin_mma, cudaFuncAttributeMaxDynamicSharedMemorySize,
                         LMA_SMEM);

    // unified init + x copy
    k_initx<<<(Nn * 16 + 255) / 256, 256>>>(x);

    k_deg_hist<<<(Ee + 255) / 256, 256>>>(col, ea);
    k_scan<<<1, 256>>>();
    k_scatter<<<(Ee + 255) / 256, 256>>>(row, col, ea);
    k_prepWbf_all<<<(139264 + 255) / 256, 256>>>(W2, Wl, W1);

    // conv1
    k_prop<4><<<(Nn * 4 + 255) / 256, 256>>>(p_hcat1, 64, 0, 16);
    k_prop<4><<<(Nn * 4 + 255) / 256, 256>>>(p_hcat1, 64, 16, 32);
    k_prop<4><<<(Nn * 4 + 255) / 256, 256>>>(p_hcat1, 64, 32, 48);
    k_gemm_conv1_mma<<<(Nn + 127) / 128, 256, CMA_SMEM>>>(p_hcat1, b1, p_xcat,
                                                          p_stats, p_stats + 128);
    k_h0<<<(Nn * 32 + 255) / 256, 256>>>(gamma1, beta1);

    // conv2
    k_prop<32><<<(Nn * 32 + 255) / 256, 256>>>(p_hcat2, 512, 0, 128);
    k_prop<32><<<(Nn * 32 + 255) / 256, 256>>>(p_hcat2, 512, 128, 256);
    k_prop<32><<<(Nn * 32 + 255) / 256, 256>>>(p_hcat2, 512, 256, 384);
    k_gemm_conv2_mma<<<(Nn + 127) / 128, 256, MMA_SMEM>>>(p_hcat2, b2, p_xcat + 128,
                                                          p_stats + 256, p_stats + 384);

    // lin1 (BN params inline from raw stats)
    dim3 glin((Nn + 127) / 128, 2);
    k_gemm_lin_mma<<<glin, 256, LMA_SMEM>>>(p_xcat, bl, batch,
                                            gamma1, beta1, gamma2, beta2,
                                            p_stats + 512, p_stats + 768);

    // merged head
    k_head1<<<Gg, 256>>>(gammal, betal, Wf1, bf1);
    k_head2<<<Gg, 128>>>(gammaf1, betaf1, Wf2, bf2);
    k_logits<<<Gg, 128>>>(gammaf2, betaf2, Wf3, bf3, out);
}